// round 4
// baseline (speedup 1.0000x reference)
#include <cuda_runtime.h>
#include <cuda_bf16.h>
#include <cstdint>

// ---------------------------------------------------------------- constants
#define BATCH 4
#define SEQ   2048
#define DMODEL 512
#define NHEAD 8
#define HDIM  64
#define MROWS 8192
#define QKV_N 1536

typedef __nv_bfloat16 bf16;

// ---------------------------------------------------------------- scratch
__device__ bf16 g_xh[(size_t)MROWS * DMODEL];
__device__ bf16 g_xl[(size_t)MROWS * DMODEL];
__device__ bf16 g_wqh[(size_t)DMODEL * QKV_N];
__device__ bf16 g_wql[(size_t)DMODEL * QKV_N];
__device__ bf16 g_woh[(size_t)DMODEL * DMODEL];
__device__ bf16 g_wol[(size_t)DMODEL * DMODEL];
__device__ bf16 g_qh[(size_t)BATCH * NHEAD * SEQ * HDIM];
__device__ bf16 g_ql[(size_t)BATCH * NHEAD * SEQ * HDIM];
__device__ bf16 g_kh[(size_t)BATCH * NHEAD * SEQ * HDIM];
__device__ bf16 g_kl[(size_t)BATCH * NHEAD * SEQ * HDIM];
__device__ bf16 g_vh[(size_t)BATCH * NHEAD * SEQ * HDIM];
__device__ bf16 g_vl[(size_t)BATCH * NHEAD * SEQ * HDIM];
__device__ bf16 g_aoh[(size_t)MROWS * DMODEL];
__device__ bf16 g_aol[(size_t)MROWS * DMODEL];

// ---------------------------------------------------------------- helpers
__device__ __forceinline__ uint32_t smem_u32(const void* p) {
    uint32_t a;
    asm("{ .reg .u64 t; cvta.to.shared.u64 t, %1; cvt.u32.u64 %0, t; }"
        : "=r"(a) : "l"(p));
    return a;
}
__device__ __forceinline__ void ldm_x4(uint32_t* r, uint32_t addr) {
    asm volatile("ldmatrix.sync.aligned.m8n8.x4.shared.b16 {%0,%1,%2,%3}, [%4];"
                 : "=r"(r[0]), "=r"(r[1]), "=r"(r[2]), "=r"(r[3]) : "r"(addr));
}
__device__ __forceinline__ void ldm_x4_t(uint32_t* r, uint32_t addr) {
    asm volatile("ldmatrix.sync.aligned.m8n8.x4.trans.shared.b16 {%0,%1,%2,%3}, [%4];"
                 : "=r"(r[0]), "=r"(r[1]), "=r"(r[2]), "=r"(r[3]) : "r"(addr));
}
__device__ __forceinline__ void mma16816(float* d, const uint32_t* a, const uint32_t* b) {
    asm volatile(
        "mma.sync.aligned.m16n8k16.row.col.f32.bf16.bf16.f32 "
        "{%0,%1,%2,%3}, {%4,%5,%6,%7}, {%8,%9}, {%0,%1,%2,%3};"
        : "+f"(d[0]), "+f"(d[1]), "+f"(d[2]), "+f"(d[3])
        : "r"(a[0]), "r"(a[1]), "r"(a[2]), "r"(a[3]), "r"(b[0]), "r"(b[1]));
}
__device__ __forceinline__ uint32_t pack_hi(float a, float b) {
    __nv_bfloat162 h = __floats2bfloat162_rn(a, b);
    return *reinterpret_cast<uint32_t*>(&h);
}
__device__ __forceinline__ uint32_t pack_lo(float a, float b, uint32_t hi) {
    __nv_bfloat162 h = *reinterpret_cast<__nv_bfloat162*>(&hi);
    float la = a - __bfloat162float(h.x);
    float lb = b - __bfloat162float(h.y);
    __nv_bfloat162 l = __floats2bfloat162_rn(la, lb);
    return *reinterpret_cast<uint32_t*>(&l);
}

#define CP16(dst, src) \
    asm volatile("cp.async.cg.shared.global [%0], [%1], 16;" :: "r"(dst), "l"(src))
#define CP_COMMIT() asm volatile("cp.async.commit_group;" ::: "memory")
#define CP_WAIT(n)  asm volatile("cp.async.wait_group %0;" :: "n"(n) : "memory")

// ---------------------------------------------------------------- convert
__global__ __launch_bounds__(256)
void convert_k(const float4* __restrict__ src, uint2* __restrict__ hi,
               uint2* __restrict__ lo, int n4) {
    const int i = blockIdx.x * 256 + threadIdx.x;
    if (i < n4) {
        float4 v = src[i];
        uint2 h, l;
        h.x = pack_hi(v.x, v.y); l.x = pack_lo(v.x, v.y, h.x);
        h.y = pack_hi(v.z, v.w); l.y = pack_lo(v.z, v.w, h.y);
        hi[i] = h; lo[i] = l;
    }
}

// ---------------------------------------------------------------- GEMM (HMMA, bf16 in)
// C[M,N] = A[M,512] @ W[512,N] (+bias). BM=128 BN=128 BK=32, 8 warps (4m x 2n).
// Stage layout (37888 B each, x2): AH[128x40]@0, AL@10240, BH[32x136]@20480, BL@29184.
template <int MODE>
__global__ __launch_bounds__(256)
void gemm_mma(const bf16* __restrict__ Ah, const bf16* __restrict__ Al,
              const bf16* __restrict__ Bh, const bf16* __restrict__ Bl,
              const float* __restrict__ bias, float* __restrict__ C, int N) {
    extern __shared__ char sm[];
    const uint32_t sbase = smem_u32(sm);
    const int tid = threadIdx.x, lane = tid & 31, w = tid >> 5;
    const int wm = w >> 1, wn = w & 1;
    const int m0 = blockIdx.y * 128, n0 = blockIdx.x * 128;

    float acc[2][8][4];
#pragma unroll
    for (int i = 0; i < 2; i++)
#pragma unroll
        for (int j = 0; j < 8; j++)
#pragma unroll
            for (int e = 0; e < 4; e++) acc[i][j][e] = 0.f;

    auto issue = [&](int kt, int buf) {
        const uint32_t base = sbase + buf * 37888;
#pragma unroll
        for (int t = 0; t < 2; t++) {
            const int q = tid * 2 + t;          // 0..511
            const int row = q >> 2, c = q & 3;  // A: 128 rows x 4 chunks
            const size_t so = (size_t)(m0 + row) * 512 + kt * 32 + c * 8;
            CP16(base + row * 80 + c * 16, Ah + so);
            CP16(base + 10240 + row * 80 + c * 16, Al + so);
            const int br = q >> 4, bc = q & 15; // B: 32 rows x 16 chunks
            const size_t bo = (size_t)(kt * 32 + br) * N + n0 + bc * 8;
            CP16(base + 20480 + br * 272 + bc * 16, Bh + bo);
            CP16(base + 29184 + br * 272 + bc * 16, Bl + bo);
        }
        CP_COMMIT();
    };

    issue(0, 0);
    for (int kt = 0; kt < 16; kt++) {
        if (kt < 15) { issue(kt + 1, (kt + 1) & 1); CP_WAIT(1); }
        else CP_WAIT(0);
        __syncthreads();
        const uint32_t bA = sbase + (kt & 1) * 37888;
#pragma unroll
        for (int ks = 0; ks < 2; ks++) {
            uint32_t ah[2][4], al[2][4];
#pragma unroll
            for (int mf = 0; mf < 2; mf++) {
                const uint32_t ra = bA +
                    ((wm * 32 + mf * 16 + (lane & 15)) * 40 + ks * 16 + (lane >> 4) * 8) * 2;
                ldm_x4(ah[mf], ra);
                ldm_x4(al[mf], ra + 10240);
            }
            uint32_t bh[4][4], bl[4][4];
#pragma unroll
            for (int g = 0; g < 4; g++) {
                const uint32_t rb = bA + 20480 +
                    ((ks * 16 + (lane & 15)) * 136 + wn * 64 + g * 16 + (lane >> 4) * 8) * 2;
                ldm_x4_t(bh[g], rb);
                ldm_x4_t(bl[g], rb + 8704);
            }
#pragma unroll
            for (int mf = 0; mf < 2; mf++)
#pragma unroll
                for (int nf = 0; nf < 8; nf++) {
                    const int g = nf >> 1, o = (nf & 1) * 2;
                    uint32_t bhf[2] = {bh[g][o], bh[g][o + 1]};
                    uint32_t blf[2] = {bl[g][o], bl[g][o + 1]};
                    mma16816(acc[mf][nf], ah[mf], bhf);
                    mma16816(acc[mf][nf], ah[mf], blf);
                    mma16816(acc[mf][nf], al[mf], bhf);
                }
        }
        __syncthreads();
    }

    // epilogue
#pragma unroll
    for (int mf = 0; mf < 2; mf++)
#pragma unroll
        for (int nf = 0; nf < 8; nf++) {
            const int col = n0 + wn * 64 + nf * 8 + (lane & 3) * 2;
            const float b0 = bias[col], b1 = bias[col + 1];
#pragma unroll
            for (int rr = 0; rr < 2; rr++) {
                const int row = m0 + wm * 32 + mf * 16 + (lane >> 2) + rr * 8;
                float v0 = acc[mf][nf][rr * 2] + b0;
                float v1 = acc[mf][nf][rr * 2 + 1] + b1;
                if (MODE == 0) {
                    const int part = col >> 9, ww = col & 511;
                    const int h = ww >> 6, hd = ww & 63;
                    const int bb = row >> 11, sidx = row & 2047;
                    if (part == 0) { v0 *= 0.125f; v1 *= 0.125f; }
                    bf16* dh = (part == 0) ? g_qh : (part == 1) ? g_kh : g_vh;
                    bf16* dl = (part == 0) ? g_ql : (part == 1) ? g_kl : g_vl;
                    const size_t idx =
                        ((((size_t)bb * NHEAD + h) * SEQ) + sidx) * HDIM + hd;
                    const uint32_t hv = pack_hi(v0, v1);
                    *reinterpret_cast<uint32_t*>(dh + idx) = hv;
                    *reinterpret_cast<uint32_t*>(dl + idx) = pack_lo(v0, v1, hv);
                } else {
                    *reinterpret_cast<float2*>(C + (size_t)row * N + col) =
                        make_float2(v0, v1);
                }
            }
        }
}

// ---------------------------------------------------------------- attention (HMMA, bf16 in)
// CTA = (128 q-rows, bh), 8 warps; warp = 16 q-rows; K-block 64, double-buffered KV.
// Smem: QH@0, QL@18432 (128x72 rows); stage s @ 36864+s*36864:
//   KH@+0, KL@+9216, VH@+18432, VL@+27648 (64x72 rows each).
__global__ __launch_bounds__(256)
void attn_mma() {
    extern __shared__ char sm[];
    const uint32_t sbase = smem_u32(sm);
    const int tid = threadIdx.x, lane = tid & 31, w = tid >> 5;
    const int qb = blockIdx.x, bh = blockIdx.y;

    const size_t hbase = (size_t)bh * SEQ * HDIM;
    const bf16* Qh = g_qh + hbase + (size_t)qb * 128 * HDIM;
    const bf16* Ql = g_ql + hbase + (size_t)qb * 128 * HDIM;

    // issue Q (group 0)
    {
#pragma unroll
        for (int t = 0; t < 4; t++) {
            const int q = tid * 4 + t;          // 0..1023
            const int row = q >> 3, c = q & 7;
            const size_t so = (size_t)row * 64 + c * 8;
            CP16(sbase + row * 144 + c * 16, Qh + so);
            CP16(sbase + 18432 + row * 144 + c * 16, Ql + so);
        }
        CP_COMMIT();
    }
    auto issueKV = [&](int kb, int buf) {
        const uint32_t base = sbase + 36864 + buf * 36864;
        const int k0 = kb * 64;
        const bf16* srcs[4] = {g_kh + hbase, g_kl + hbase, g_vh + hbase, g_vl + hbase};
#pragma unroll
        for (int a = 0; a < 4; a++) {
#pragma unroll
            for (int t = 0; t < 2; t++) {
                const int q = tid * 2 + t;      // 0..511
                const int row = q >> 3, c = q & 7;
                CP16(base + a * 9216 + row * 144 + c * 16,
                     srcs[a] + (size_t)(k0 + row) * 64 + c * 8);
            }
        }
        CP_COMMIT();
    };

    const int nkb = 2 * qb + 2;
    issueKV(0, 0);
    CP_WAIT(1);  // Q ready
    __syncthreads();

    uint32_t qh[4][4], ql[4][4];
#pragma unroll
    for (int ks = 0; ks < 4; ks++) {
        const uint32_t ra = sbase +
            ((w * 16 + (lane & 15)) * 72 + ks * 16 + (lane >> 4) * 8) * 2;
        ldm_x4(qh[ks], ra);
        ldm_x4(ql[ks], ra + 18432);
    }

    float oacc[8][4];
#pragma unroll
    for (int j = 0; j < 8; j++)
#pragma unroll
        for (int e = 0; e < 4; e++) oacc[j][e] = 0.f;
    float mrow[2] = {-1e30f, -1e30f};
    float lrow[2] = {0.f, 0.f};
    const int qi0 = qb * 128 + w * 16 + (lane >> 2);

    for (int kb = 0; kb < nkb; kb++) {
        const int k0 = kb * 64;
        if (kb + 1 < nkb) { issueKV(kb + 1, (kb + 1) & 1); CP_WAIT(1); }
        else CP_WAIT(0);
        __syncthreads();
        const uint32_t kvb = sbase + 36864 + (kb & 1) * 36864;

        if (qb * 128 + w * 16 + 15 >= k0) {
            // S = Q K^T
            float sacc[8][4];
#pragma unroll
            for (int j = 0; j < 8; j++)
#pragma unroll
                for (int e = 0; e < 4; e++) sacc[j][e] = 0.f;
#pragma unroll
            for (int ks = 0; ks < 4; ks++) {
                uint32_t kh[4][4], kl[4][4];
#pragma unroll
                for (int g = 0; g < 4; g++) {
                    const uint32_t rb = kvb +
                        ((g * 16 + (lane & 15)) * 72 + ks * 16 + (lane >> 4) * 8) * 2;
                    ldm_x4(kh[g], rb);
                    ldm_x4(kl[g], rb + 9216);
                }
#pragma unroll
                for (int nf = 0; nf < 8; nf++) {
                    const int g = nf >> 1, o = nf & 1;
                    uint32_t bhf[2] = {kh[g][o], kh[g][o + 2]};
                    uint32_t blf[2] = {kl[g][o], kl[g][o + 2]};
                    mma16816(sacc[nf], qh[ks], bhf);
                    mma16816(sacc[nf], qh[ks], blf);
                    mma16816(sacc[nf], ql[ks], bhf);
                }
            }
            // online softmax
            float mx[2] = {-1e30f, -1e30f};
#pragma unroll
            for (int nf = 0; nf < 8; nf++)
#pragma unroll
                for (int e = 0; e < 4; e++) {
                    const int col = k0 + nf * 8 + (lane & 3) * 2 + (e & 1);
                    const int r = e >> 1;
                    if (col > qi0 + r * 8) sacc[nf][e] = -1e30f;
                    else mx[r] = fmaxf(mx[r], sacc[nf][e]);
                }
#pragma unroll
            for (int r = 0; r < 2; r++) {
                mx[r] = fmaxf(mx[r], __shfl_xor_sync(0xffffffffu, mx[r], 1));
                mx[r] = fmaxf(mx[r], __shfl_xor_sync(0xffffffffu, mx[r], 2));
            }
            float mn[2], corr[2], sum[2] = {0.f, 0.f};
#pragma unroll
            for (int r = 0; r < 2; r++) {
                mn[r] = fmaxf(mrow[r], mx[r]);
                corr[r] = __expf(mrow[r] - mn[r]);
                mrow[r] = mn[r];
            }
#pragma unroll
            for (int nf = 0; nf < 8; nf++)
#pragma unroll
                for (int e = 0; e < 4; e++) {
                    const int r = e >> 1;
                    const float p = __expf(sacc[nf][e] - mn[r]);
                    sacc[nf][e] = p;
                    sum[r] += p;
                }
#pragma unroll
            for (int r = 0; r < 2; r++) {
                sum[r] += __shfl_xor_sync(0xffffffffu, sum[r], 1);
                sum[r] += __shfl_xor_sync(0xffffffffu, sum[r], 2);
                lrow[r] = lrow[r] * corr[r] + sum[r];
            }
#pragma unroll
            for (int nf = 0; nf < 8; nf++)
#pragma unroll
                for (int e = 0; e < 4; e++) oacc[nf][e] *= corr[e >> 1];
            // PV
#pragma unroll
            for (int ks = 0; ks < 4; ks++) {
                uint32_t ph[4], pl[4];
                ph[0] = pack_hi(sacc[2 * ks][0], sacc[2 * ks][1]);
                pl[0] = pack_lo(sacc[2 * ks][0], sacc[2 * ks][1], ph[0]);
                ph[1] = pack_hi(sacc[2 * ks][2], sacc[2 * ks][3]);
                pl[1] = pack_lo(sacc[2 * ks][2], sacc[2 * ks][3], ph[1]);
                ph[2] = pack_hi(sacc[2 * ks + 1][0], sacc[2 * ks + 1][1]);
                pl[2] = pack_lo(sacc[2 * ks + 1][0], sacc[2 * ks + 1][1], ph[2]);
                ph[3] = pack_hi(sacc[2 * ks + 1][2], sacc[2 * ks + 1][3]);
                pl[3] = pack_lo(sacc[2 * ks + 1][2], sacc[2 * ks + 1][3], ph[3]);
                uint32_t vh[4][4], vl[4][4];
#pragma unroll
                for (int g = 0; g < 4; g++) {
                    const uint32_t rb = kvb + 18432 +
                        ((ks * 16 + (lane & 15)) * 72 + g * 16 + (lane >> 4) * 8) * 2;
                    ldm_x4_t(vh[g], rb);
                    ldm_x4_t(vl[g], rb + 9216);
                }
#pragma unroll
                for (int nf = 0; nf < 8; nf++) {
                    const int g = nf >> 1, o = (nf & 1) * 2;
                    uint32_t bhf[2] = {vh[g][o], vh[g][o + 1]};
                    uint32_t blf[2] = {vl[g][o], vl[g][o + 1]};
                    mma16816(oacc[nf], ph, bhf);
                    mma16816(oacc[nf], ph, blf);
                    mma16816(oacc[nf], pl, bhf);
                }
            }
        }
        __syncthreads();
    }

    // write out as bf16 hi/lo (input of out-proj GEMM)
    const int bb = bh >> 3, h = bh & 7;
#pragma unroll
    for (int r = 0; r < 2; r++) {
        const float inv = 1.f / lrow[r];
        const int qi = qi0 + r * 8;
        const size_t rowoff = ((size_t)bb * SEQ + qi) * DMODEL + h * HDIM;
#pragma unroll
        for (int nf = 0; nf < 8; nf++) {
            const int hd = nf * 8 + (lane & 3) * 2;
            const float v0 = oacc[nf][r * 2] * inv;
            const float v1 = oacc[nf][r * 2 + 1] * inv;
            const uint32_t hv = pack_hi(v0, v1);
            *reinterpret_cast<uint32_t*>(g_aoh + rowoff + hd) = hv;
            *reinterpret_cast<uint32_t*>(g_aol + rowoff + hd) = pack_lo(v0, v1, hv);
        }
    }
}

// ---------------------------------------------------------------- launch
extern "C" void kernel_launch(void* const* d_in, const int* in_sizes, int n_in,
                              void* d_out, int out_size) {
    const float* x     = (const float*)d_in[0];
    const float* w_qkv = (const float*)d_in[1];
    const float* b_qkv = (const float*)d_in[2];
    const float* w_out = (const float*)d_in[3];
    const float* b_out = (const float*)d_in[4];
    float* out = (float*)d_out;

    bf16 *xh, *xl, *wqh, *wql, *woh, *wol, *aoh, *aol;
    cudaGetSymbolAddress((void**)&xh, g_xh);   cudaGetSymbolAddress((void**)&xl, g_xl);
    cudaGetSymbolAddress((void**)&wqh, g_wqh); cudaGetSymbolAddress((void**)&wql, g_wql);
    cudaGetSymbolAddress((void**)&woh, g_woh); cudaGetSymbolAddress((void**)&wol, g_wol);
    cudaGetSymbolAddress((void**)&aoh, g_aoh); cudaGetSymbolAddress((void**)&aol, g_aol);

    const int SMEM_GEMM = 75776;
    const int SMEM_ATT  = 110592;
    cudaFuncSetAttribute(gemm_mma<0>, cudaFuncAttributeMaxDynamicSharedMemorySize, SMEM_GEMM);
    cudaFuncSetAttribute(gemm_mma<1>, cudaFuncAttributeMaxDynamicSharedMemorySize, SMEM_GEMM);
    cudaFuncSetAttribute(attn_mma,    cudaFuncAttributeMaxDynamicSharedMemorySize, SMEM_ATT);

    // pre-convert inputs (fp32 -> bf16 hi/lo)
    convert_k<<<(MROWS * DMODEL / 4 + 255) / 256, 256>>>(
        (const float4*)x, (uint2*)xh, (uint2*)xl, MROWS * DMODEL / 4);
    convert_k<<<(DMODEL * QKV_N / 4 + 255) / 256, 256>>>(
        (const float4*)w_qkv, (uint2*)wqh, (uint2*)wql, DMODEL * QKV_N / 4);
    convert_k<<<(DMODEL * DMODEL / 4 + 255) / 256, 256>>>(
        (const float4*)w_out, (uint2*)woh, (uint2*)wol, DMODEL * DMODEL / 4);

    // 1) QKV projection -> q/k/v bf16 hi/lo (Q pre-scaled)
    gemm_mma<0><<<dim3(QKV_N / 128, MROWS / 128), 256, SMEM_GEMM>>>(
        xh, xl, wqh, wql, b_qkv, nullptr, QKV_N);
    // 2) causal attention -> g_aoh/g_aol
    attn_mma<<<dim3(SEQ / 128, BATCH * NHEAD), 256, SMEM_ATT>>>();
    // 3) output projection -> fp32 out
    gemm_mma<1><<<dim3(DMODEL / 128, MROWS / 128), 256, SMEM_GEMM>>>(
        aoh, aol, woh, wol, b_out, out, DMODEL);
}

// round 5
// speedup vs baseline: 1.0163x; 1.0163x over previous
#include <cuda_runtime.h>
#include <cuda_bf16.h>
#include <cstdint>

// ---------------------------------------------------------------- constants
#define BATCH 4
#define SEQ   2048
#define DMODEL 512
#define NHEAD 8
#define HDIM  64
#define MROWS 8192
#define QKV_N 1536

typedef __nv_bfloat16 bf16;

// ---------------------------------------------------------------- scratch
__device__ bf16 g_xh[(size_t)MROWS * DMODEL];
__device__ bf16 g_xl[(size_t)MROWS * DMODEL];
__device__ bf16 g_wqh[(size_t)DMODEL * QKV_N];
__device__ bf16 g_wql[(size_t)DMODEL * QKV_N];
__device__ bf16 g_woh[(size_t)DMODEL * DMODEL];
__device__ bf16 g_wol[(size_t)DMODEL * DMODEL];
__device__ bf16 g_qh[(size_t)BATCH * NHEAD * SEQ * HDIM];
__device__ bf16 g_ql[(size_t)BATCH * NHEAD * SEQ * HDIM];
__device__ bf16 g_kh[(size_t)BATCH * NHEAD * SEQ * HDIM];
__device__ bf16 g_kl[(size_t)BATCH * NHEAD * SEQ * HDIM];
__device__ bf16 g_vh[(size_t)BATCH * NHEAD * SEQ * HDIM];
__device__ bf16 g_vl[(size_t)BATCH * NHEAD * SEQ * HDIM];
__device__ bf16 g_aoh[(size_t)MROWS * DMODEL];
__device__ bf16 g_aol[(size_t)MROWS * DMODEL];

// ---------------------------------------------------------------- helpers
__device__ __forceinline__ uint32_t smem_u32(const void* p) {
    uint32_t a;
    asm("{ .reg .u64 t; cvta.to.shared.u64 t, %1; cvt.u32.u64 %0, t; }"
        : "=r"(a) : "l"(p));
    return a;
}
__device__ __forceinline__ void ldm_x4(uint32_t* r, uint32_t addr) {
    asm volatile("ldmatrix.sync.aligned.m8n8.x4.shared.b16 {%0,%1,%2,%3}, [%4];"
                 : "=r"(r[0]), "=r"(r[1]), "=r"(r[2]), "=r"(r[3]) : "r"(addr));
}
__device__ __forceinline__ void ldm_x4_t(uint32_t* r, uint32_t addr) {
    asm volatile("ldmatrix.sync.aligned.m8n8.x4.trans.shared.b16 {%0,%1,%2,%3}, [%4];"
                 : "=r"(r[0]), "=r"(r[1]), "=r"(r[2]), "=r"(r[3]) : "r"(addr));
}
__device__ __forceinline__ void mma16816(float* d, const uint32_t* a, const uint32_t* b) {
    asm volatile(
        "mma.sync.aligned.m16n8k16.row.col.f32.bf16.bf16.f32 "
        "{%0,%1,%2,%3}, {%4,%5,%6,%7}, {%8,%9}, {%0,%1,%2,%3};"
        : "+f"(d[0]), "+f"(d[1]), "+f"(d[2]), "+f"(d[3])
        : "r"(a[0]), "r"(a[1]), "r"(a[2]), "r"(a[3]), "r"(b[0]), "r"(b[1]));
}
__device__ __forceinline__ uint32_t pack_hi(float a, float b) {
    __nv_bfloat162 h = __floats2bfloat162_rn(a, b);
    return *reinterpret_cast<uint32_t*>(&h);
}
__device__ __forceinline__ uint32_t pack_lo(float a, float b, uint32_t hi) {
    __nv_bfloat162 h = *reinterpret_cast<__nv_bfloat162*>(&hi);
    float la = a - __bfloat162float(h.x);
    float lb = b - __bfloat162float(h.y);
    __nv_bfloat162 l = __floats2bfloat162_rn(la, lb);
    return *reinterpret_cast<uint32_t*>(&l);
}

#define CP16(dst, src) \
    asm volatile("cp.async.cg.shared.global [%0], [%1], 16;" :: "r"(dst), "l"(src))
#define CP_COMMIT() asm volatile("cp.async.commit_group;" ::: "memory")
#define CP_WAIT(n)  asm volatile("cp.async.wait_group %0;" :: "n"(n) : "memory")

// ---------------------------------------------------------------- convert
__global__ __launch_bounds__(256)
void convert_k(const float4* __restrict__ src, uint2* __restrict__ hi,
               uint2* __restrict__ lo, int n4) {
    const int i = blockIdx.x * 256 + threadIdx.x;
    if (i < n4) {
        float4 v = src[i];
        uint2 h, l;
        h.x = pack_hi(v.x, v.y); l.x = pack_lo(v.x, v.y, h.x);
        h.y = pack_hi(v.z, v.w); l.y = pack_lo(v.z, v.w, h.y);
        hi[i] = h; lo[i] = l;
    }
}

// ---------------------------------------------------------------- GEMM (HMMA, bf16 in)
// C[M,N] = A[M,512] @ W[512,N] (+bias). BM=128 BN=128 BK=32, 8 warps (4m x 2n).
// Register-staged prefetch + double-buffered smem.
// Buffer (37888 B): AH[128x40]@0, AL@10240, BH[32x136]@20480, BL@29184.
template <int MODE>
__global__ __launch_bounds__(256)
void gemm_mma(const bf16* __restrict__ Ah, const bf16* __restrict__ Al,
              const bf16* __restrict__ Bh, const bf16* __restrict__ Bl,
              const float* __restrict__ bias, float* __restrict__ C, int N) {
    extern __shared__ char sm[];
    const uint32_t sbase = smem_u32(sm);
    const int tid = threadIdx.x, lane = tid & 31, w = tid >> 5;
    const int wm = w >> 1, wn = w & 1;
    const int m0 = blockIdx.y * 128, n0 = blockIdx.x * 128;

    float acc[2][8][4];
#pragma unroll
    for (int i = 0; i < 2; i++)
#pragma unroll
        for (int j = 0; j < 8; j++)
#pragma unroll
            for (int e = 0; e < 4; e++) acc[i][j][e] = 0.f;

    // staging registers: 2 A chunks (hi+lo) + 2 B chunks (hi+lo)
    uint4 sAh[2], sAl[2], sBh[2], sBl[2];
    const int aq0 = tid * 2;               // A chunk ids {aq0, aq0+1}
    const int arow0 = aq0 >> 2, ac0 = aq0 & 3;
    const int arow1 = (aq0 + 1) >> 2, ac1 = (aq0 + 1) & 3;
    const int br0 = aq0 >> 4, bc0 = aq0 & 15;
    const int br1 = (aq0 + 1) >> 4, bc1 = (aq0 + 1) & 15;

    auto loadG = [&](int kt) {
        const size_t a0 = (size_t)(m0 + arow0) * 512 + kt * 32 + ac0 * 8;
        const size_t a1 = (size_t)(m0 + arow1) * 512 + kt * 32 + ac1 * 8;
        sAh[0] = *reinterpret_cast<const uint4*>(Ah + a0);
        sAh[1] = *reinterpret_cast<const uint4*>(Ah + a1);
        sAl[0] = *reinterpret_cast<const uint4*>(Al + a0);
        sAl[1] = *reinterpret_cast<const uint4*>(Al + a1);
        const size_t b0 = (size_t)(kt * 32 + br0) * N + n0 + bc0 * 8;
        const size_t b1 = (size_t)(kt * 32 + br1) * N + n0 + bc1 * 8;
        sBh[0] = *reinterpret_cast<const uint4*>(Bh + b0);
        sBh[1] = *reinterpret_cast<const uint4*>(Bh + b1);
        sBl[0] = *reinterpret_cast<const uint4*>(Bl + b0);
        sBl[1] = *reinterpret_cast<const uint4*>(Bl + b1);
    };
    auto storeS = [&](int buf) {
        char* b = sm + buf * 37888;
        *reinterpret_cast<uint4*>(b + (arow0 * 40 + ac0 * 8) * 2) = sAh[0];
        *reinterpret_cast<uint4*>(b + (arow1 * 40 + ac1 * 8) * 2) = sAh[1];
        *reinterpret_cast<uint4*>(b + 10240 + (arow0 * 40 + ac0 * 8) * 2) = sAl[0];
        *reinterpret_cast<uint4*>(b + 10240 + (arow1 * 40 + ac1 * 8) * 2) = sAl[1];
        *reinterpret_cast<uint4*>(b + 20480 + (br0 * 136 + bc0 * 8) * 2) = sBh[0];
        *reinterpret_cast<uint4*>(b + 20480 + (br1 * 136 + bc1 * 8) * 2) = sBh[1];
        *reinterpret_cast<uint4*>(b + 29184 + (br0 * 136 + bc0 * 8) * 2) = sBl[0];
        *reinterpret_cast<uint4*>(b + 29184 + (br1 * 136 + bc1 * 8) * 2) = sBl[1];
    };

    loadG(0);
    storeS(0);
    __syncthreads();

    for (int kt = 0; kt < 16; kt++) {
        const int cur = kt & 1;
        if (kt < 15) loadG(kt + 1);
        const uint32_t bA = sbase + cur * 37888;
#pragma unroll
        for (int ks = 0; ks < 2; ks++) {
            uint32_t ah[2][4], al[2][4];
#pragma unroll
            for (int mf = 0; mf < 2; mf++) {
                const uint32_t ra = bA +
                    ((wm * 32 + mf * 16 + (lane & 15)) * 40 + ks * 16 + (lane >> 4) * 8) * 2;
                ldm_x4(ah[mf], ra);
                ldm_x4(al[mf], ra + 10240);
            }
            uint32_t bh[4][4], bl[4][4];
#pragma unroll
            for (int g = 0; g < 4; g++) {
                const uint32_t rb = bA + 20480 +
                    ((ks * 16 + (lane & 15)) * 136 + wn * 64 + g * 16 + (lane >> 4) * 8) * 2;
                ldm_x4_t(bh[g], rb);
                ldm_x4_t(bl[g], rb + 8704);
            }
            // pass 1: ah*bh (16 independent MMAs)
#pragma unroll
            for (int mf = 0; mf < 2; mf++)
#pragma unroll
                for (int nf = 0; nf < 8; nf++) {
                    const int g = nf >> 1, o = (nf & 1) * 2;
                    uint32_t bhf[2] = {bh[g][o], bh[g][o + 1]};
                    mma16816(acc[mf][nf], ah[mf], bhf);
                }
            // pass 2: ah*bl
#pragma unroll
            for (int mf = 0; mf < 2; mf++)
#pragma unroll
                for (int nf = 0; nf < 8; nf++) {
                    const int g = nf >> 1, o = (nf & 1) * 2;
                    uint32_t blf[2] = {bl[g][o], bl[g][o + 1]};
                    mma16816(acc[mf][nf], ah[mf], blf);
                }
            // pass 3: al*bh
#pragma unroll
            for (int mf = 0; mf < 2; mf++)
#pragma unroll
                for (int nf = 0; nf < 8; nf++) {
                    const int g = nf >> 1, o = (nf & 1) * 2;
                    uint32_t bhf[2] = {bh[g][o], bh[g][o + 1]};
                    mma16816(acc[mf][nf], al[mf], bhf);
                }
        }
        if (kt < 15) storeS(cur ^ 1);
        __syncthreads();
    }

    // epilogue
#pragma unroll
    for (int mf = 0; mf < 2; mf++)
#pragma unroll
        for (int nf = 0; nf < 8; nf++) {
            const int col = n0 + wn * 64 + nf * 8 + (lane & 3) * 2;
            const float b0 = bias[col], b1 = bias[col + 1];
#pragma unroll
            for (int rr = 0; rr < 2; rr++) {
                const int row = m0 + wm * 32 + mf * 16 + (lane >> 2) + rr * 8;
                float v0 = acc[mf][nf][rr * 2] + b0;
                float v1 = acc[mf][nf][rr * 2 + 1] + b1;
                if (MODE == 0) {
                    const int part = col >> 9, ww = col & 511;
                    const int h = ww >> 6, hd = ww & 63;
                    const int bb = row >> 11, sidx = row & 2047;
                    if (part == 0) { v0 *= 0.125f; v1 *= 0.125f; }
                    bf16* dh = (part == 0) ? g_qh : (part == 1) ? g_kh : g_vh;
                    bf16* dl = (part == 0) ? g_ql : (part == 1) ? g_kl : g_vl;
                    const size_t idx =
                        ((((size_t)bb * NHEAD + h) * SEQ) + sidx) * HDIM + hd;
                    const uint32_t hv = pack_hi(v0, v1);
                    *reinterpret_cast<uint32_t*>(dh + idx) = hv;
                    *reinterpret_cast<uint32_t*>(dl + idx) = pack_lo(v0, v1, hv);
                } else {
                    *reinterpret_cast<float2*>(C + (size_t)row * N + col) =
                        make_float2(v0, v1);
                }
            }
        }
}

// ---------------------------------------------------------------- attention (HMMA, bf16 in)
// CTA = (128 q-rows, bh), 8 warps; warp = 16 q-rows; K-block 64, double-buffered KV.
// Smem: QH@0, QL@18432 (128 rows x 72); stage s @ 36864+s*36864:
//   KH@+0, KL@+9216, VH@+18432, VL@+27648 (64 rows x 72 each).
__global__ __launch_bounds__(256)
void attn_mma() {
    extern __shared__ char sm[];
    const uint32_t sbase = smem_u32(sm);
    const int tid = threadIdx.x, lane = tid & 31, w = tid >> 5;
    const int qb = blockIdx.x, bh = blockIdx.y;

    const size_t hbase = (size_t)bh * SEQ * HDIM;
    const bf16* Qh = g_qh + hbase + (size_t)qb * 128 * HDIM;
    const bf16* Ql = g_ql + hbase + (size_t)qb * 128 * HDIM;

    // issue Q (group 0)
    {
#pragma unroll
        for (int t = 0; t < 4; t++) {
            const int q = tid * 4 + t;          // 0..1023
            const int row = q >> 3, c = q & 7;
            const size_t so = (size_t)row * 64 + c * 8;
            CP16(sbase + row * 144 + c * 16, Qh + so);
            CP16(sbase + 18432 + row * 144 + c * 16, Ql + so);
        }
        CP_COMMIT();
    }
    auto issueKV = [&](int kb, int buf) {
        const uint32_t base = sbase + 36864 + buf * 36864;
        const int k0 = kb * 64;
        const bf16* srcs[4] = {g_kh + hbase, g_kl + hbase, g_vh + hbase, g_vl + hbase};
#pragma unroll
        for (int a = 0; a < 4; a++) {
#pragma unroll
            for (int t = 0; t < 2; t++) {
                const int q = tid * 2 + t;      // 0..511
                const int row = q >> 3, c = q & 7;
                CP16(base + a * 9216 + row * 144 + c * 16,
                     srcs[a] + (size_t)(k0 + row) * 64 + c * 8);
            }
        }
        CP_COMMIT();
    };

    const int nkb = 2 * qb + 2;
    issueKV(0, 0);
    CP_WAIT(1);  // Q ready
    __syncthreads();

    uint32_t qh[4][4], ql[4][4];
#pragma unroll
    for (int ks = 0; ks < 4; ks++) {
        const uint32_t ra = sbase +
            ((w * 16 + (lane & 15)) * 72 + ks * 16 + (lane >> 4) * 8) * 2;
        ldm_x4(qh[ks], ra);
        ldm_x4(ql[ks], ra + 18432);
    }

    float oacc[8][4];
#pragma unroll
    for (int j = 0; j < 8; j++)
#pragma unroll
        for (int e = 0; e < 4; e++) oacc[j][e] = 0.f;
    float mrow[2] = {-1e30f, -1e30f};
    float lrow[2] = {0.f, 0.f};
    const int qi0 = qb * 128 + w * 16 + (lane >> 2);

    for (int kb = 0; kb < nkb; kb++) {
        const int k0 = kb * 64;
        if (kb + 1 < nkb) { issueKV(kb + 1, (kb + 1) & 1); CP_WAIT(1); }
        else CP_WAIT(0);
        __syncthreads();
        const uint32_t kvb = sbase + 36864 + (kb & 1) * 36864;

        if (qb * 128 + w * 16 + 15 >= k0) {
            // ---- S = Q K^T
            float sacc[8][4];
#pragma unroll
            for (int j = 0; j < 8; j++)
#pragma unroll
                for (int e = 0; e < 4; e++) sacc[j][e] = 0.f;
#pragma unroll
            for (int ks = 0; ks < 4; ks++) {
                uint32_t kh[4][4], kl[4][4];
#pragma unroll
                for (int g = 0; g < 4; g++) {
                    const uint32_t rb = kvb +
                        ((g * 16 + (lane & 15)) * 72 + ks * 16 + (lane >> 4) * 8) * 2;
                    ldm_x4(kh[g], rb);
                    ldm_x4(kl[g], rb + 9216);
                }
                // three passes of 8 independent MMAs each
#pragma unroll
                for (int nf = 0; nf < 8; nf++) {
                    const int g = nf >> 1, o = nf & 1;
                    uint32_t bhf[2] = {kh[g][o], kh[g][o + 2]};
                    mma16816(sacc[nf], qh[ks], bhf);
                }
#pragma unroll
                for (int nf = 0; nf < 8; nf++) {
                    const int g = nf >> 1, o = nf & 1;
                    uint32_t blf[2] = {kl[g][o], kl[g][o + 2]};
                    mma16816(sacc[nf], qh[ks], blf);
                }
#pragma unroll
                for (int nf = 0; nf < 8; nf++) {
                    const int g = nf >> 1, o = nf & 1;
                    uint32_t bhf[2] = {kh[g][o], kh[g][o + 2]};
                    mma16816(sacc[nf], ql[ks], bhf);
                }
            }
            // ---- online softmax
            float mx[2] = {-1e30f, -1e30f};
#pragma unroll
            for (int nf = 0; nf < 8; nf++)
#pragma unroll
                for (int e = 0; e < 4; e++) {
                    const int col = k0 + nf * 8 + (lane & 3) * 2 + (e & 1);
                    const int r = e >> 1;
                    if (col > qi0 + r * 8) sacc[nf][e] = -1e30f;
                    else mx[r] = fmaxf(mx[r], sacc[nf][e]);
                }
#pragma unroll
            for (int r = 0; r < 2; r++) {
                mx[r] = fmaxf(mx[r], __shfl_xor_sync(0xffffffffu, mx[r], 1));
                mx[r] = fmaxf(mx[r], __shfl_xor_sync(0xffffffffu, mx[r], 2));
            }
            float mn[2], corr[2], sum[2] = {0.f, 0.f};
#pragma unroll
            for (int r = 0; r < 2; r++) {
                mn[r] = fmaxf(mrow[r], mx[r]);
                corr[r] = __expf(mrow[r] - mn[r]);
                mrow[r] = mn[r];
            }
#pragma unroll
            for (int nf = 0; nf < 8; nf++)
#pragma unroll
                for (int e = 0; e < 4; e++) {
                    const int r = e >> 1;
                    const float p = __expf(sacc[nf][e] - mn[r]);
                    sacc[nf][e] = p;
                    sum[r] += p;
                }
#pragma unroll
            for (int r = 0; r < 2; r++) {
                sum[r] += __shfl_xor_sync(0xffffffffu, sum[r], 1);
                sum[r] += __shfl_xor_sync(0xffffffffu, sum[r], 2);
                lrow[r] = lrow[r] * corr[r] + sum[r];
            }
#pragma unroll
            for (int nf = 0; nf < 8; nf++)
#pragma unroll
                for (int e = 0; e < 4; e++) oacc[nf][e] *= corr[e >> 1];
            // ---- PV
#pragma unroll
            for (int ks = 0; ks < 4; ks++) {
                uint32_t ph[4], pl[4];
                ph[0] = pack_hi(sacc[2 * ks][0], sacc[2 * ks][1]);
                pl[0] = pack_lo(sacc[2 * ks][0], sacc[2 * ks][1], ph[0]);
                ph[1] = pack_hi(sacc[2 * ks][2], sacc[2 * ks][3]);
                pl[1] = pack_lo(sacc[2 * ks][2], sacc[2 * ks][3], ph[1]);
                ph[2] = pack_hi(sacc[2 * ks + 1][0], sacc[2 * ks + 1][1]);
                pl[2] = pack_lo(sacc[2 * ks + 1][0], sacc[2 * ks + 1][1], ph[2]);
                ph[3] = pack_hi(sacc[2 * ks + 1][2], sacc[2 * ks + 1][3]);
                pl[3] = pack_lo(sacc[2 * ks + 1][2], sacc[2 * ks + 1][3], ph[3]);
                uint32_t vh[4][4], vl[4][4];
#pragma unroll
                for (int g = 0; g < 4; g++) {
                    const uint32_t rb = kvb + 18432 +
                        ((ks * 16 + (lane & 15)) * 72 + g * 16 + (lane >> 4) * 8) * 2;
                    ldm_x4_t(vh[g], rb);
                    ldm_x4_t(vl[g], rb + 9216);
                }
                // three passes of 8 independent MMAs each
#pragma unroll
                for (int nf = 0; nf < 8; nf++) {
                    const int g = nf >> 1, o = (nf & 1) * 2;
                    uint32_t bhf[2] = {vh[g][o], vh[g][o + 1]};
                    mma16816(oacc[nf], ph, bhf);
                }
#pragma unroll
                for (int nf = 0; nf < 8; nf++) {
                    const int g = nf >> 1, o = (nf & 1) * 2;
                    uint32_t blf[2] = {vl[g][o], vl[g][o + 1]};
                    mma16816(oacc[nf], ph, blf);
                }
#pragma unroll
                for (int nf = 0; nf < 8; nf++) {
                    const int g = nf >> 1, o = (nf & 1) * 2;
                    uint32_t bhf[2] = {vh[g][o], vh[g][o + 1]};
                    mma16816(oacc[nf], pl, bhf);
                }
            }
        }
        __syncthreads();
    }

    // write out as bf16 hi/lo (input of out-proj GEMM)
    const int bb = bh >> 3, h = bh & 7;
#pragma unroll
    for (int r = 0; r < 2; r++) {
        const float inv = 1.f / lrow[r];
        const int qi = qi0 + r * 8;
        const size_t rowoff = ((size_t)bb * SEQ + qi) * DMODEL + h * HDIM;
#pragma unroll
        for (int nf = 0; nf < 8; nf++) {
            const int hd = nf * 8 + (lane & 3) * 2;
            const float v0 = oacc[nf][r * 2] * inv;
            const float v1 = oacc[nf][r * 2 + 1] * inv;
            const uint32_t hv = pack_hi(v0, v1);
            *reinterpret_cast<uint32_t*>(g_aoh + rowoff + hd) = hv;
            *reinterpret_cast<uint32_t*>(g_aol + rowoff + hd) = pack_lo(v0, v1, hv);
        }
    }
}

// ---------------------------------------------------------------- launch
extern "C" void kernel_launch(void* const* d_in, const int* in_sizes, int n_in,
                              void* d_out, int out_size) {
    const float* x     = (const float*)d_in[0];
    const float* w_qkv = (const float*)d_in[1];
    const float* b_qkv = (const float*)d_in[2];
    const float* w_out = (const float*)d_in[3];
    const float* b_out = (const float*)d_in[4];
    float* out = (float*)d_out;

    bf16 *xh, *xl, *wqh, *wql, *woh, *wol, *aoh, *aol;
    cudaGetSymbolAddress((void**)&xh, g_xh);   cudaGetSymbolAddress((void**)&xl, g_xl);
    cudaGetSymbolAddress((void**)&wqh, g_wqh); cudaGetSymbolAddress((void**)&wql, g_wql);
    cudaGetSymbolAddress((void**)&woh, g_woh); cudaGetSymbolAddress((void**)&wol, g_wol);
    cudaGetSymbolAddress((void**)&aoh, g_aoh); cudaGetSymbolAddress((void**)&aol, g_aol);

    const int SMEM_GEMM = 75776;
    const int SMEM_ATT  = 110592;
    cudaFuncSetAttribute(gemm_mma<0>, cudaFuncAttributeMaxDynamicSharedMemorySize, SMEM_GEMM);
    cudaFuncSetAttribute(gemm_mma<1>, cudaFuncAttributeMaxDynamicSharedMemorySize, SMEM_GEMM);
    cudaFuncSetAttribute(attn_mma,    cudaFuncAttributeMaxDynamicSharedMemorySize, SMEM_ATT);

    // pre-convert inputs (fp32 -> bf16 hi/lo)
    convert_k<<<(MROWS * DMODEL / 4 + 255) / 256, 256>>>(
        (const float4*)x, (uint2*)xh, (uint2*)xl, MROWS * DMODEL / 4);
    convert_k<<<(DMODEL * QKV_N / 4 + 255) / 256, 256>>>(
        (const float4*)w_qkv, (uint2*)wqh, (uint2*)wql, DMODEL * QKV_N / 4);
    convert_k<<<(DMODEL * DMODEL / 4 + 255) / 256, 256>>>(
        (const float4*)w_out, (uint2*)woh, (uint2*)wol, DMODEL * DMODEL / 4);

    // 1) QKV projection -> q/k/v bf16 hi/lo (Q pre-scaled)
    gemm_mma<0><<<dim3(QKV_N / 128, MROWS / 128), 256, SMEM_GEMM>>>(
        xh, xl, wqh, wql, b_qkv, nullptr, QKV_N);
    // 2) causal attention -> g_aoh/g_aol
    attn_mma<<<dim3(SEQ / 128, BATCH * NHEAD), 256, SMEM_ATT>>>();
    // 3) output projection -> fp32 out
    gemm_mma<1><<<dim3(DMODEL / 128, MROWS / 128), 256, SMEM_GEMM>>>(
        aoh, aol, woh, wol, b_out, out, DMODEL);
}

// round 6
// speedup vs baseline: 1.1158x; 1.0979x over previous
#include <cuda_runtime.h>
#include <cuda_bf16.h>
#include <cstdint>

// ---------------------------------------------------------------- constants
#define BATCH 4
#define SEQ   2048
#define DMODEL 512
#define NHEAD 8
#define HDIM  64
#define MROWS 8192
#define QKV_N 1536

typedef __nv_bfloat16 bf16;

// ---------------------------------------------------------------- scratch
__device__ bf16 g_xh[(size_t)MROWS * DMODEL];
__device__ bf16 g_xl[(size_t)MROWS * DMODEL];
__device__ bf16 g_wqh[(size_t)DMODEL * QKV_N];
__device__ bf16 g_wql[(size_t)DMODEL * QKV_N];
__device__ bf16 g_woh[(size_t)DMODEL * DMODEL];
__device__ bf16 g_wol[(size_t)DMODEL * DMODEL];
__device__ bf16 g_qh[(size_t)BATCH * NHEAD * SEQ * HDIM];
__device__ bf16 g_ql[(size_t)BATCH * NHEAD * SEQ * HDIM];
__device__ bf16 g_kh[(size_t)BATCH * NHEAD * SEQ * HDIM];
__device__ bf16 g_kl[(size_t)BATCH * NHEAD * SEQ * HDIM];
__device__ bf16 g_vh[(size_t)BATCH * NHEAD * SEQ * HDIM];
__device__ bf16 g_vl[(size_t)BATCH * NHEAD * SEQ * HDIM];
__device__ bf16 g_aoh[(size_t)MROWS * DMODEL];
__device__ bf16 g_aol[(size_t)MROWS * DMODEL];

// ---------------------------------------------------------------- helpers
__device__ __forceinline__ uint32_t smem_u32(const void* p) {
    uint32_t a;
    asm("{ .reg .u64 t; cvta.to.shared.u64 t, %1; cvt.u32.u64 %0, t; }"
        : "=r"(a) : "l"(p));
    return a;
}
__device__ __forceinline__ void ldm_x4(uint32_t* r, uint32_t addr) {
    asm volatile("ldmatrix.sync.aligned.m8n8.x4.shared.b16 {%0,%1,%2,%3}, [%4];"
                 : "=r"(r[0]), "=r"(r[1]), "=r"(r[2]), "=r"(r[3]) : "r"(addr));
}
__device__ __forceinline__ void ldm_x4_t(uint32_t* r, uint32_t addr) {
    asm volatile("ldmatrix.sync.aligned.m8n8.x4.trans.shared.b16 {%0,%1,%2,%3}, [%4];"
                 : "=r"(r[0]), "=r"(r[1]), "=r"(r[2]), "=r"(r[3]) : "r"(addr));
}
__device__ __forceinline__ void mma16816(float* d, const uint32_t* a, const uint32_t* b) {
    asm volatile(
        "mma.sync.aligned.m16n8k16.row.col.f32.bf16.bf16.f32 "
        "{%0,%1,%2,%3}, {%4,%5,%6,%7}, {%8,%9}, {%0,%1,%2,%3};"
        : "+f"(d[0]), "+f"(d[1]), "+f"(d[2]), "+f"(d[3])
        : "r"(a[0]), "r"(a[1]), "r"(a[2]), "r"(a[3]), "r"(b[0]), "r"(b[1]));
}
__device__ __forceinline__ uint32_t pack_hi(float a, float b) {
    __nv_bfloat162 h = __floats2bfloat162_rn(a, b);
    return *reinterpret_cast<uint32_t*>(&h);
}
__device__ __forceinline__ uint32_t pack_lo(float a, float b, uint32_t hi) {
    __nv_bfloat162 h = *reinterpret_cast<__nv_bfloat162*>(&hi);
    float la = a - __bfloat162float(h.x);
    float lb = b - __bfloat162float(h.y);
    __nv_bfloat162 l = __floats2bfloat162_rn(la, lb);
    return *reinterpret_cast<uint32_t*>(&l);
}

#define CP16(dst, src) \
    asm volatile("cp.async.cg.shared.global [%0], [%1], 16;" :: "r"(dst), "l"(src))
#define CP_COMMIT() asm volatile("cp.async.commit_group;" ::: "memory")
#define CP_WAIT(n)  asm volatile("cp.async.wait_group %0;" :: "n"(n) : "memory")

// ---------------------------------------------------------------- convert
__global__ __launch_bounds__(256)
void convert_k(const float4* __restrict__ src, uint2* __restrict__ hi,
               uint2* __restrict__ lo, int n4) {
    const int i = blockIdx.x * 256 + threadIdx.x;
    if (i < n4) {
        float4 v = src[i];
        uint2 h, l;
        h.x = pack_hi(v.x, v.y); l.x = pack_lo(v.x, v.y, h.x);
        h.y = pack_hi(v.z, v.w); l.y = pack_lo(v.z, v.w, h.y);
        hi[i] = h; lo[i] = l;
    }
}

// ---------------------------------------------------------------- GEMM (HMMA, bf16 in)
// C[M,N] = A[M,512] @ W[512,N] (+bias). BM=128 BN=128 BK=32, 8 warps (4m x 2n).
// Register-staged prefetch + double-buffered smem; R3 serial MMA order.
// Buffer (37888 B): AH[128x40]@0, AL@10240, BH[32x136]@20480, BL@29184.
template <int MODE>
__global__ __launch_bounds__(256)
void gemm_mma(const bf16* __restrict__ Ah, const bf16* __restrict__ Al,
              const bf16* __restrict__ Bh, const bf16* __restrict__ Bl,
              const float* __restrict__ bias, float* __restrict__ C, int N) {
    extern __shared__ char sm[];
    const uint32_t sbase = smem_u32(sm);
    const int tid = threadIdx.x, lane = tid & 31, w = tid >> 5;
    const int wm = w >> 1, wn = w & 1;
    const int m0 = blockIdx.y * 128, n0 = blockIdx.x * 128;

    float acc[2][8][4];
#pragma unroll
    for (int i = 0; i < 2; i++)
#pragma unroll
        for (int j = 0; j < 8; j++)
#pragma unroll
            for (int e = 0; e < 4; e++) acc[i][j][e] = 0.f;

    uint4 sAh[2], sAl[2], sBh[2], sBl[2];
    const int aq0 = tid * 2;
    const int arow0 = aq0 >> 2, ac0 = aq0 & 3;
    const int arow1 = (aq0 + 1) >> 2, ac1 = (aq0 + 1) & 3;
    const int br0 = aq0 >> 4, bc0 = aq0 & 15;
    const int br1 = (aq0 + 1) >> 4, bc1 = (aq0 + 1) & 15;

    auto loadG = [&](int kt) {
        const size_t a0 = (size_t)(m0 + arow0) * 512 + kt * 32 + ac0 * 8;
        const size_t a1 = (size_t)(m0 + arow1) * 512 + kt * 32 + ac1 * 8;
        sAh[0] = *reinterpret_cast<const uint4*>(Ah + a0);
        sAh[1] = *reinterpret_cast<const uint4*>(Ah + a1);
        sAl[0] = *reinterpret_cast<const uint4*>(Al + a0);
        sAl[1] = *reinterpret_cast<const uint4*>(Al + a1);
        const size_t b0 = (size_t)(kt * 32 + br0) * N + n0 + bc0 * 8;
        const size_t b1 = (size_t)(kt * 32 + br1) * N + n0 + bc1 * 8;
        sBh[0] = *reinterpret_cast<const uint4*>(Bh + b0);
        sBh[1] = *reinterpret_cast<const uint4*>(Bh + b1);
        sBl[0] = *reinterpret_cast<const uint4*>(Bl + b0);
        sBl[1] = *reinterpret_cast<const uint4*>(Bl + b1);
    };
    auto storeS = [&](int buf) {
        char* b = sm + buf * 37888;
        *reinterpret_cast<uint4*>(b + (arow0 * 40 + ac0 * 8) * 2) = sAh[0];
        *reinterpret_cast<uint4*>(b + (arow1 * 40 + ac1 * 8) * 2) = sAh[1];
        *reinterpret_cast<uint4*>(b + 10240 + (arow0 * 40 + ac0 * 8) * 2) = sAl[0];
        *reinterpret_cast<uint4*>(b + 10240 + (arow1 * 40 + ac1 * 8) * 2) = sAl[1];
        *reinterpret_cast<uint4*>(b + 20480 + (br0 * 136 + bc0 * 8) * 2) = sBh[0];
        *reinterpret_cast<uint4*>(b + 20480 + (br1 * 136 + bc1 * 8) * 2) = sBh[1];
        *reinterpret_cast<uint4*>(b + 29184 + (br0 * 136 + bc0 * 8) * 2) = sBl[0];
        *reinterpret_cast<uint4*>(b + 29184 + (br1 * 136 + bc1 * 8) * 2) = sBl[1];
    };

    loadG(0);
    storeS(0);
    __syncthreads();

    for (int kt = 0; kt < 16; kt++) {
        const int cur = kt & 1;
        if (kt < 15) loadG(kt + 1);
        const uint32_t bA = sbase + cur * 37888;
#pragma unroll
        for (int ks = 0; ks < 2; ks++) {
            uint32_t ah[2][4], al[2][4];
#pragma unroll
            for (int mf = 0; mf < 2; mf++) {
                const uint32_t ra = bA +
                    ((wm * 32 + mf * 16 + (lane & 15)) * 40 + ks * 16 + (lane >> 4) * 8) * 2;
                ldm_x4(ah[mf], ra);
                ldm_x4(al[mf], ra + 10240);
            }
            uint32_t bh[4][4], bl[4][4];
#pragma unroll
            for (int g = 0; g < 4; g++) {
                const uint32_t rb = bA + 20480 +
                    ((ks * 16 + (lane & 15)) * 136 + wn * 64 + g * 16 + (lane >> 4) * 8) * 2;
                ldm_x4_t(bh[g], rb);
                ldm_x4_t(bl[g], rb + 8704);
            }
#pragma unroll
            for (int mf = 0; mf < 2; mf++)
#pragma unroll
                for (int nf = 0; nf < 8; nf++) {
                    const int g = nf >> 1, o = (nf & 1) * 2;
                    uint32_t bhf[2] = {bh[g][o], bh[g][o + 1]};
                    uint32_t blf[2] = {bl[g][o], bl[g][o + 1]};
                    mma16816(acc[mf][nf], ah[mf], bhf);
                    mma16816(acc[mf][nf], ah[mf], blf);
                    mma16816(acc[mf][nf], al[mf], bhf);
                }
        }
        if (kt < 15) storeS(cur ^ 1);
        __syncthreads();
    }

    // epilogue
#pragma unroll
    for (int mf = 0; mf < 2; mf++)
#pragma unroll
        for (int nf = 0; nf < 8; nf++) {
            const int col = n0 + wn * 64 + nf * 8 + (lane & 3) * 2;
            const float b0 = bias[col], b1 = bias[col + 1];
#pragma unroll
            for (int rr = 0; rr < 2; rr++) {
                const int row = m0 + wm * 32 + mf * 16 + (lane >> 2) + rr * 8;
                float v0 = acc[mf][nf][rr * 2] + b0;
                float v1 = acc[mf][nf][rr * 2 + 1] + b1;
                if (MODE == 0) {
                    const int part = col >> 9, ww = col & 511;
                    const int h = ww >> 6, hd = ww & 63;
                    const int bb = row >> 11, sidx = row & 2047;
                    if (part == 0) { v0 *= 0.125f; v1 *= 0.125f; }
                    bf16* dh = (part == 0) ? g_qh : (part == 1) ? g_kh : g_vh;
                    bf16* dl = (part == 0) ? g_ql : (part == 1) ? g_kl : g_vl;
                    const size_t idx =
                        ((((size_t)bb * NHEAD + h) * SEQ) + sidx) * HDIM + hd;
                    const uint32_t hv = pack_hi(v0, v1);
                    *reinterpret_cast<uint32_t*>(dh + idx) = hv;
                    *reinterpret_cast<uint32_t*>(dl + idx) = pack_lo(v0, v1, hv);
                } else {
                    *reinterpret_cast<float2*>(C + (size_t)row * N + col) =
                        make_float2(v0, v1);
                }
            }
        }
}

// ---------------------------------------------------------------- attention (HMMA, bf16 in)
// Single balanced wave: grid (4, 32). CTA p handles q-blocks {p, 15-p, 4+p, 11-p}
// (68 k-block iterations each, exactly equal). 8 warps; warp = 16 q-rows.
// Smem: QH@0, QL@18432 (128 rows x 72); KV stage s @ 36864+s*36864:
//   KH@+0, KL@+9216, VH@+18432, VL@+27648 (64 rows x 72 each).
__global__ __launch_bounds__(256)
void attn_mma() {
    extern __shared__ char sm[];
    const uint32_t sbase = smem_u32(sm);
    const int tid = threadIdx.x, lane = tid & 31, w = tid >> 5;
    const int p = blockIdx.x, bh = blockIdx.y;

    const size_t hbase = (size_t)bh * SEQ * HDIM;
    const int qlist[4] = {p, 15 - p, 4 + p, 11 - p};

    auto issueKV = [&](int kb, int buf) {
        const uint32_t base = sbase + 36864 + buf * 36864;
        const int k0 = kb * 64;
        const bf16* srcs[4] = {g_kh + hbase, g_kl + hbase, g_vh + hbase, g_vl + hbase};
#pragma unroll
        for (int a = 0; a < 4; a++) {
#pragma unroll
            for (int t = 0; t < 2; t++) {
                const int q = tid * 2 + t;
                const int row = q >> 3, c = q & 7;
                CP16(base + a * 9216 + row * 144 + c * 16,
                     srcs[a] + (size_t)(k0 + row) * 64 + c * 8);
            }
        }
        CP_COMMIT();
    };

    for (int qq = 0; qq < 4; qq++) {
        const int qb = qlist[qq];
        const bf16* Qh = g_qh + hbase + (size_t)qb * 128 * HDIM;
        const bf16* Ql = g_ql + hbase + (size_t)qb * 128 * HDIM;

        // issue Q
#pragma unroll
        for (int t = 0; t < 4; t++) {
            const int q = tid * 4 + t;
            const int row = q >> 3, c = q & 7;
            const size_t so = (size_t)row * 64 + c * 8;
            CP16(sbase + row * 144 + c * 16, Qh + so);
            CP16(sbase + 18432 + row * 144 + c * 16, Ql + so);
        }
        CP_COMMIT();

        const int nkb = 2 * qb + 2;
        issueKV(0, 0);
        CP_WAIT(1);  // Q ready
        __syncthreads();

        uint32_t qh[4][4], ql[4][4];
#pragma unroll
        for (int ks = 0; ks < 4; ks++) {
            const uint32_t ra = sbase +
                ((w * 16 + (lane & 15)) * 72 + ks * 16 + (lane >> 4) * 8) * 2;
            ldm_x4(qh[ks], ra);
            ldm_x4(ql[ks], ra + 18432);
        }

        float oacc[8][4];
#pragma unroll
        for (int j = 0; j < 8; j++)
#pragma unroll
            for (int e = 0; e < 4; e++) oacc[j][e] = 0.f;
        float mrow[2] = {-1e30f, -1e30f};
        float lrow[2] = {0.f, 0.f};
        const int qi0 = qb * 128 + w * 16 + (lane >> 2);

        for (int kb = 0; kb < nkb; kb++) {
            const int k0 = kb * 64;
            if (kb + 1 < nkb) { issueKV(kb + 1, (kb + 1) & 1); CP_WAIT(1); }
            else CP_WAIT(0);
            __syncthreads();
            const uint32_t kvb = sbase + 36864 + (kb & 1) * 36864;

            if (qb * 128 + w * 16 + 15 >= k0) {
                // ---- S = Q K^T
                float sacc[8][4];
#pragma unroll
                for (int j = 0; j < 8; j++)
#pragma unroll
                    for (int e = 0; e < 4; e++) sacc[j][e] = 0.f;
#pragma unroll
                for (int ks = 0; ks < 4; ks++) {
                    uint32_t kh[4][4], kl[4][4];
#pragma unroll
                    for (int g = 0; g < 4; g++) {
                        const uint32_t rb = kvb +
                            ((g * 16 + (lane & 15)) * 72 + ks * 16 + (lane >> 4) * 8) * 2;
                        ldm_x4(kh[g], rb);
                        ldm_x4(kl[g], rb + 9216);
                    }
#pragma unroll
                    for (int nf = 0; nf < 8; nf++) {
                        const int g = nf >> 1, o = nf & 1;
                        uint32_t bhf[2] = {kh[g][o], kh[g][o + 2]};
                        uint32_t blf[2] = {kl[g][o], kl[g][o + 2]};
                        mma16816(sacc[nf], qh[ks], bhf);
                        mma16816(sacc[nf], qh[ks], blf);
                        mma16816(sacc[nf], ql[ks], bhf);
                    }
                }
                // ---- online softmax
                float mx[2] = {-1e30f, -1e30f};
#pragma unroll
                for (int nf = 0; nf < 8; nf++)
#pragma unroll
                    for (int e = 0; e < 4; e++) {
                        const int col = k0 + nf * 8 + (lane & 3) * 2 + (e & 1);
                        const int r = e >> 1;
                        if (col > qi0 + r * 8) sacc[nf][e] = -1e30f;
                        else mx[r] = fmaxf(mx[r], sacc[nf][e]);
                    }
#pragma unroll
                for (int r = 0; r < 2; r++) {
                    mx[r] = fmaxf(mx[r], __shfl_xor_sync(0xffffffffu, mx[r], 1));
                    mx[r] = fmaxf(mx[r], __shfl_xor_sync(0xffffffffu, mx[r], 2));
                }
                float mn[2], corr[2], sum[2] = {0.f, 0.f};
#pragma unroll
                for (int r = 0; r < 2; r++) {
                    mn[r] = fmaxf(mrow[r], mx[r]);
                    corr[r] = __expf(mrow[r] - mn[r]);
                    mrow[r] = mn[r];
                }
#pragma unroll
                for (int nf = 0; nf < 8; nf++)
#pragma unroll
                    for (int e = 0; e < 4; e++) {
                        const int r = e >> 1;
                        const float pv = __expf(sacc[nf][e] - mn[r]);
                        sacc[nf][e] = pv;
                        sum[r] += pv;
                    }
#pragma unroll
                for (int r = 0; r < 2; r++) {
                    sum[r] += __shfl_xor_sync(0xffffffffu, sum[r], 1);
                    sum[r] += __shfl_xor_sync(0xffffffffu, sum[r], 2);
                    lrow[r] = lrow[r] * corr[r] + sum[r];
                }
#pragma unroll
                for (int nf = 0; nf < 8; nf++)
#pragma unroll
                    for (int e = 0; e < 4; e++) oacc[nf][e] *= corr[e >> 1];
                // ---- PV
#pragma unroll
                for (int ks = 0; ks < 4; ks++) {
                    uint32_t ph[4], pl[4];
                    ph[0] = pack_hi(sacc[2 * ks][0], sacc[2 * ks][1]);
                    pl[0] = pack_lo(sacc[2 * ks][0], sacc[2 * ks][1], ph[0]);
                    ph[1] = pack_hi(sacc[2 * ks][2], sacc[2 * ks][3]);
                    pl[1] = pack_lo(sacc[2 * ks][2], sacc[2 * ks][3], ph[1]);
                    ph[2] = pack_hi(sacc[2 * ks + 1][0], sacc[2 * ks + 1][1]);
                    pl[2] = pack_lo(sacc[2 * ks + 1][0], sacc[2 * ks + 1][1], ph[2]);
                    ph[3] = pack_hi(sacc[2 * ks + 1][2], sacc[2 * ks + 1][3]);
                    pl[3] = pack_lo(sacc[2 * ks + 1][2], sacc[2 * ks + 1][3], ph[3]);
                    uint32_t vh[4][4], vl[4][4];
#pragma unroll
                    for (int g = 0; g < 4; g++) {
                        const uint32_t rb = kvb + 18432 +
                            ((ks * 16 + (lane & 15)) * 72 + g * 16 + (lane >> 4) * 8) * 2;
                        ldm_x4_t(vh[g], rb);
                        ldm_x4_t(vl[g], rb + 9216);
                    }
#pragma unroll
                    for (int nf = 0; nf < 8; nf++) {
                        const int g = nf >> 1, o = (nf & 1) * 2;
                        uint32_t bhf[2] = {vh[g][o], vh[g][o + 1]};
                        uint32_t blf[2] = {vl[g][o], vl[g][o + 1]};
                        mma16816(oacc[nf], ph, bhf);
                        mma16816(oacc[nf], ph, blf);
                        mma16816(oacc[nf], pl, bhf);
                    }
                }
            }
            __syncthreads();
        }

        // write out as bf16 hi/lo (input of out-proj GEMM)
        const int bb = bh >> 3, h = bh & 7;
#pragma unroll
        for (int r = 0; r < 2; r++) {
            const float inv = 1.f / lrow[r];
            const int qi = qi0 + r * 8;
            const size_t rowoff = ((size_t)bb * SEQ + qi) * DMODEL + h * HDIM;
#pragma unroll
            for (int nf = 0; nf < 8; nf++) {
                const int hd = nf * 8 + (lane & 3) * 2;
                const float v0 = oacc[nf][r * 2] * inv;
                const float v1 = oacc[nf][r * 2 + 1] * inv;
                const uint32_t hv = pack_hi(v0, v1);
                *reinterpret_cast<uint32_t*>(g_aoh + rowoff + hd) = hv;
                *reinterpret_cast<uint32_t*>(g_aol + rowoff + hd) = pack_lo(v0, v1, hv);
            }
        }
    }
}

// ---------------------------------------------------------------- launch
extern "C" void kernel_launch(void* const* d_in, const int* in_sizes, int n_in,
                              void* d_out, int out_size) {
    const float* x     = (const float*)d_in[0];
    const float* w_qkv = (const float*)d_in[1];
    const float* b_qkv = (const float*)d_in[2];
    const float* w_out = (const float*)d_in[3];
    const float* b_out = (const float*)d_in[4];
    float* out = (float*)d_out;

    bf16 *xh, *xl, *wqh, *wql, *woh, *wol, *aoh, *aol;
    cudaGetSymbolAddress((void**)&xh, g_xh);   cudaGetSymbolAddress((void**)&xl, g_xl);
    cudaGetSymbolAddress((void**)&wqh, g_wqh); cudaGetSymbolAddress((void**)&wql, g_wql);
    cudaGetSymbolAddress((void**)&woh, g_woh); cudaGetSymbolAddress((void**)&wol, g_wol);
    cudaGetSymbolAddress((void**)&aoh, g_aoh); cudaGetSymbolAddress((void**)&aol, g_aol);

    const int SMEM_GEMM = 75776;
    const int SMEM_ATT  = 110592;
    cudaFuncSetAttribute(gemm_mma<0>, cudaFuncAttributeMaxDynamicSharedMemorySize, SMEM_GEMM);
    cudaFuncSetAttribute(gemm_mma<1>, cudaFuncAttributeMaxDynamicSharedMemorySize, SMEM_GEMM);
    cudaFuncSetAttribute(attn_mma,    cudaFuncAttributeMaxDynamicSharedMemorySize, SMEM_ATT);

    // pre-convert inputs (fp32 -> bf16 hi/lo)
    convert_k<<<(MROWS * DMODEL / 4 + 255) / 256, 256>>>(
        (const float4*)x, (uint2*)xh, (uint2*)xl, MROWS * DMODEL / 4);
    convert_k<<<(DMODEL * QKV_N / 4 + 255) / 256, 256>>>(
        (const float4*)w_qkv, (uint2*)wqh, (uint2*)wql, DMODEL * QKV_N / 4);
    convert_k<<<(DMODEL * DMODEL / 4 + 255) / 256, 256>>>(
        (const float4*)w_out, (uint2*)woh, (uint2*)wol, DMODEL * DMODEL / 4);

    // 1) QKV projection -> q/k/v bf16 hi/lo (Q pre-scaled)
    gemm_mma<0><<<dim3(QKV_N / 128, MROWS / 128), 256, SMEM_GEMM>>>(
        xh, xl, wqh, wql, b_qkv, nullptr, QKV_N);
    // 2) causal attention (single balanced wave) -> g_aoh/g_aol
    attn_mma<<<dim3(4, BATCH * NHEAD), 256, SMEM_ATT>>>();
    // 3) output projection -> fp32 out
    gemm_mma<1><<<dim3(DMODEL / 128, MROWS / 128), 256, SMEM_GEMM>>>(
        aoh, aol, woh, wol, b_out, out, DMODEL);
}

// round 7
// speedup vs baseline: 1.1709x; 1.0494x over previous
#include <cuda_runtime.h>
#include <cuda_bf16.h>
#include <cstdint>

// ---------------------------------------------------------------- constants
#define BATCH 4
#define SEQ   2048
#define DMODEL 512
#define NHEAD 8
#define HDIM  64
#define MROWS 8192
#define QKV_N 1536

typedef __nv_bfloat16 bf16;

// ---------------------------------------------------------------- scratch
__device__ bf16 g_xh[(size_t)MROWS * DMODEL];
__device__ bf16 g_xl[(size_t)MROWS * DMODEL];
__device__ bf16 g_wqh[(size_t)DMODEL * QKV_N];
__device__ bf16 g_wql[(size_t)DMODEL * QKV_N];
__device__ bf16 g_woh[(size_t)DMODEL * DMODEL];
__device__ bf16 g_wol[(size_t)DMODEL * DMODEL];
__device__ bf16 g_qh[(size_t)BATCH * NHEAD * SEQ * HDIM];
__device__ bf16 g_ql[(size_t)BATCH * NHEAD * SEQ * HDIM];
__device__ bf16 g_kh[(size_t)BATCH * NHEAD * SEQ * HDIM];
__device__ bf16 g_kl[(size_t)BATCH * NHEAD * SEQ * HDIM];
__device__ bf16 g_vh[(size_t)BATCH * NHEAD * SEQ * HDIM];
__device__ bf16 g_vl[(size_t)BATCH * NHEAD * SEQ * HDIM];
__device__ bf16 g_aoh[(size_t)MROWS * DMODEL];
__device__ bf16 g_aol[(size_t)MROWS * DMODEL];

// ---------------------------------------------------------------- helpers
__device__ __forceinline__ uint32_t smem_u32(const void* p) {
    uint32_t a;
    asm("{ .reg .u64 t; cvta.to.shared.u64 t, %1; cvt.u32.u64 %0, t; }"
        : "=r"(a) : "l"(p));
    return a;
}
__device__ __forceinline__ void ldm_x4(uint32_t* r, uint32_t addr) {
    asm volatile("ldmatrix.sync.aligned.m8n8.x4.shared.b16 {%0,%1,%2,%3}, [%4];"
                 : "=r"(r[0]), "=r"(r[1]), "=r"(r[2]), "=r"(r[3]) : "r"(addr));
}
__device__ __forceinline__ void ldm_x4_t(uint32_t* r, uint32_t addr) {
    asm volatile("ldmatrix.sync.aligned.m8n8.x4.trans.shared.b16 {%0,%1,%2,%3}, [%4];"
                 : "=r"(r[0]), "=r"(r[1]), "=r"(r[2]), "=r"(r[3]) : "r"(addr));
}
__device__ __forceinline__ void mma16816(float* d, const uint32_t* a, const uint32_t* b) {
    asm volatile(
        "mma.sync.aligned.m16n8k16.row.col.f32.bf16.bf16.f32 "
        "{%0,%1,%2,%3}, {%4,%5,%6,%7}, {%8,%9}, {%0,%1,%2,%3};"
        : "+f"(d[0]), "+f"(d[1]), "+f"(d[2]), "+f"(d[3])
        : "r"(a[0]), "r"(a[1]), "r"(a[2]), "r"(a[3]), "r"(b[0]), "r"(b[1]));
}
__device__ __forceinline__ uint32_t pack_hi(float a, float b) {
    __nv_bfloat162 h = __floats2bfloat162_rn(a, b);
    return *reinterpret_cast<uint32_t*>(&h);
}
__device__ __forceinline__ uint32_t pack_lo(float a, float b, uint32_t hi) {
    __nv_bfloat162 h = *reinterpret_cast<__nv_bfloat162*>(&hi);
    float la = a - __bfloat162float(h.x);
    float lb = b - __bfloat162float(h.y);
    __nv_bfloat162 l = __floats2bfloat162_rn(la, lb);
    return *reinterpret_cast<uint32_t*>(&l);
}

#define CP16(dst, src) \
    asm volatile("cp.async.cg.shared.global [%0], [%1], 16;" :: "r"(dst), "l"(src))
#define CP_COMMIT() asm volatile("cp.async.commit_group;" ::: "memory")
#define CP_WAIT(n)  asm volatile("cp.async.wait_group %0;" :: "n"(n) : "memory")

// ---------------------------------------------------------------- convert
__global__ __launch_bounds__(256)
void convert_k(const float4* __restrict__ src, uint2* __restrict__ hi,
               uint2* __restrict__ lo, int n4) {
    const int i = blockIdx.x * 256 + threadIdx.x;
    if (i < n4) {
        float4 v = src[i];
        uint2 h, l;
        h.x = pack_hi(v.x, v.y); l.x = pack_lo(v.x, v.y, h.x);
        h.y = pack_hi(v.z, v.w); l.y = pack_lo(v.z, v.w, h.y);
        hi[i] = h; lo[i] = l;
    }
}

// ---------------------------------------------------------------- GEMM (HMMA, bf16 in)
// C[M,N] = A[M,512] @ W[512,N] (+bias). BM=128 BN=64 BK=32, 8 warps (4m x 2n),
// warp tile 32x32. 3-stage cp.async pipeline, 2 CTAs/SM.
// Stage (29696 B): AH[128x40]@0, AL@10240, BH[32x72]@20480, BL@25088.
#define GSTG 29696
template <int MODE>
__global__ __launch_bounds__(256, 2)
void gemm_mma(const bf16* __restrict__ Ah, const bf16* __restrict__ Al,
              const bf16* __restrict__ Bh, const bf16* __restrict__ Bl,
              const float* __restrict__ bias, float* __restrict__ C, int N) {
    extern __shared__ char sm[];
    const uint32_t sbase = smem_u32(sm);
    const int tid = threadIdx.x, lane = tid & 31, w = tid >> 5;
    const int wm = w >> 1, wn = w & 1;
    const int m0 = blockIdx.y * 128, n0 = blockIdx.x * 64;

    float acc[2][4][4];
#pragma unroll
    for (int i = 0; i < 2; i++)
#pragma unroll
        for (int j = 0; j < 4; j++)
#pragma unroll
            for (int e = 0; e < 4; e++) acc[i][j][e] = 0.f;

    // cp.async chunk mapping (per thread, per stage):
    //   A: 2 chunks of hi + 2 of lo (512 chunks total, 16B each)
    //   B: 1 chunk of hi + 1 of lo (256 chunks total)
    const int aq0 = tid * 2;
    const int ar0 = aq0 >> 2, ac0 = aq0 & 3;
    const int ar1 = (aq0 + 1) >> 2, ac1 = (aq0 + 1) & 3;
    const int br = tid >> 3, bc = tid & 7;

    auto issue = [&](int kt) {
        const uint32_t base = sbase + (kt % 3) * GSTG;
        const size_t a0 = (size_t)(m0 + ar0) * 512 + kt * 32 + ac0 * 8;
        const size_t a1 = (size_t)(m0 + ar1) * 512 + kt * 32 + ac1 * 8;
        CP16(base + ar0 * 80 + ac0 * 16, Ah + a0);
        CP16(base + ar1 * 80 + ac1 * 16, Ah + a1);
        CP16(base + 10240 + ar0 * 80 + ac0 * 16, Al + a0);
        CP16(base + 10240 + ar1 * 80 + ac1 * 16, Al + a1);
        const size_t b0 = (size_t)(kt * 32 + br) * N + n0 + bc * 8;
        CP16(base + 20480 + br * 144 + bc * 16, Bh + b0);
        CP16(base + 25088 + br * 144 + bc * 16, Bl + b0);
        CP_COMMIT();
    };

    issue(0);
    issue(1);
    for (int kt = 0; kt < 16; kt++) {
        CP_WAIT(1);
        __syncthreads();
        if (kt + 2 < 16) issue(kt + 2);
        const uint32_t bA = sbase + (kt % 3) * GSTG;
#pragma unroll
        for (int ks = 0; ks < 2; ks++) {
            uint32_t ah[2][4], al[2][4];
#pragma unroll
            for (int mf = 0; mf < 2; mf++) {
                const uint32_t ra = bA +
                    ((wm * 32 + mf * 16 + (lane & 15)) * 40 + ks * 16 + (lane >> 4) * 8) * 2;
                ldm_x4(ah[mf], ra);
                ldm_x4(al[mf], ra + 10240);
            }
            uint32_t bh[2][4], bl[2][4];
#pragma unroll
            for (int g = 0; g < 2; g++) {
                const uint32_t rb = bA + 20480 +
                    ((ks * 16 + (lane & 15)) * 72 + wn * 32 + g * 16 + (lane >> 4) * 8) * 2;
                ldm_x4_t(bh[g], rb);
                ldm_x4_t(bl[g], rb + 4608);
            }
#pragma unroll
            for (int mf = 0; mf < 2; mf++)
#pragma unroll
                for (int nf = 0; nf < 4; nf++) {
                    const int g = nf >> 1, o = (nf & 1) * 2;
                    uint32_t bhf[2] = {bh[g][o], bh[g][o + 1]};
                    uint32_t blf[2] = {bl[g][o], bl[g][o + 1]};
                    mma16816(acc[mf][nf], ah[mf], bhf);
                    mma16816(acc[mf][nf], ah[mf], blf);
                    mma16816(acc[mf][nf], al[mf], bhf);
                }
        }
        __syncthreads();
    }

    // epilogue
#pragma unroll
    for (int mf = 0; mf < 2; mf++)
#pragma unroll
        for (int nf = 0; nf < 4; nf++) {
            const int col = n0 + wn * 32 + nf * 8 + (lane & 3) * 2;
            const float b0 = bias[col], b1 = bias[col + 1];
#pragma unroll
            for (int rr = 0; rr < 2; rr++) {
                const int row = m0 + wm * 32 + mf * 16 + (lane >> 2) + rr * 8;
                float v0 = acc[mf][nf][rr * 2] + b0;
                float v1 = acc[mf][nf][rr * 2 + 1] + b1;
                if (MODE == 0) {
                    const int part = col >> 9, ww = col & 511;
                    const int h = ww >> 6, hd = ww & 63;
                    const int bb = row >> 11, sidx = row & 2047;
                    if (part == 0) { v0 *= 0.125f; v1 *= 0.125f; }
                    bf16* dh = (part == 0) ? g_qh : (part == 1) ? g_kh : g_vh;
                    bf16* dl = (part == 0) ? g_ql : (part == 1) ? g_kl : g_vl;
                    const size_t idx =
                        ((((size_t)bb * NHEAD + h) * SEQ) + sidx) * HDIM + hd;
                    const uint32_t hv = pack_hi(v0, v1);
                    *reinterpret_cast<uint32_t*>(dh + idx) = hv;
                    *reinterpret_cast<uint32_t*>(dl + idx) = pack_lo(v0, v1, hv);
                } else {
                    *reinterpret_cast<float2*>(C + (size_t)row * N + col) =
                        make_float2(v0, v1);
                }
            }
        }
}

// ---------------------------------------------------------------- attention (HMMA, bf16 in)
// Single balanced wave: grid (4, 32). CTA p handles q-blocks {p, 15-p, 4+p, 11-p}
// (68 k-block iterations each). 8 warps; warp = 16 q-rows. (unchanged from R6)
__global__ __launch_bounds__(256)
void attn_mma() {
    extern __shared__ char sm[];
    const uint32_t sbase = smem_u32(sm);
    const int tid = threadIdx.x, lane = tid & 31, w = tid >> 5;
    const int p = blockIdx.x, bh = blockIdx.y;

    const size_t hbase = (size_t)bh * SEQ * HDIM;
    const int qlist[4] = {p, 15 - p, 4 + p, 11 - p};

    auto issueKV = [&](int kb, int buf) {
        const uint32_t base = sbase + 36864 + buf * 36864;
        const int k0 = kb * 64;
        const bf16* srcs[4] = {g_kh + hbase, g_kl + hbase, g_vh + hbase, g_vl + hbase};
#pragma unroll
        for (int a = 0; a < 4; a++) {
#pragma unroll
            for (int t = 0; t < 2; t++) {
                const int q = tid * 2 + t;
                const int row = q >> 3, c = q & 7;
                CP16(base + a * 9216 + row * 144 + c * 16,
                     srcs[a] + (size_t)(k0 + row) * 64 + c * 8);
            }
        }
        CP_COMMIT();
    };

    for (int qq = 0; qq < 4; qq++) {
        const int qb = qlist[qq];
        const bf16* Qh = g_qh + hbase + (size_t)qb * 128 * HDIM;
        const bf16* Ql = g_ql + hbase + (size_t)qb * 128 * HDIM;

#pragma unroll
        for (int t = 0; t < 4; t++) {
            const int q = tid * 4 + t;
            const int row = q >> 3, c = q & 7;
            const size_t so = (size_t)row * 64 + c * 8;
            CP16(sbase + row * 144 + c * 16, Qh + so);
            CP16(sbase + 18432 + row * 144 + c * 16, Ql + so);
        }
        CP_COMMIT();

        const int nkb = 2 * qb + 2;
        issueKV(0, 0);
        CP_WAIT(1);
        __syncthreads();

        uint32_t qh[4][4], ql[4][4];
#pragma unroll
        for (int ks = 0; ks < 4; ks++) {
            const uint32_t ra = sbase +
                ((w * 16 + (lane & 15)) * 72 + ks * 16 + (lane >> 4) * 8) * 2;
            ldm_x4(qh[ks], ra);
            ldm_x4(ql[ks], ra + 18432);
        }

        float oacc[8][4];
#pragma unroll
        for (int j = 0; j < 8; j++)
#pragma unroll
            for (int e = 0; e < 4; e++) oacc[j][e] = 0.f;
        float mrow[2] = {-1e30f, -1e30f};
        float lrow[2] = {0.f, 0.f};
        const int qi0 = qb * 128 + w * 16 + (lane >> 2);

        for (int kb = 0; kb < nkb; kb++) {
            const int k0 = kb * 64;
            if (kb + 1 < nkb) { issueKV(kb + 1, (kb + 1) & 1); CP_WAIT(1); }
            else CP_WAIT(0);
            __syncthreads();
            const uint32_t kvb = sbase + 36864 + (kb & 1) * 36864;

            if (qb * 128 + w * 16 + 15 >= k0) {
                float sacc[8][4];
#pragma unroll
                for (int j = 0; j < 8; j++)
#pragma unroll
                    for (int e = 0; e < 4; e++) sacc[j][e] = 0.f;
#pragma unroll
                for (int ks = 0; ks < 4; ks++) {
                    uint32_t kh[4][4], kl[4][4];
#pragma unroll
                    for (int g = 0; g < 4; g++) {
                        const uint32_t rb = kvb +
                            ((g * 16 + (lane & 15)) * 72 + ks * 16 + (lane >> 4) * 8) * 2;
                        ldm_x4(kh[g], rb);
                        ldm_x4(kl[g], rb + 9216);
                    }
#pragma unroll
                    for (int nf = 0; nf < 8; nf++) {
                        const int g = nf >> 1, o = nf & 1;
                        uint32_t bhf[2] = {kh[g][o], kh[g][o + 2]};
                        uint32_t blf[2] = {kl[g][o], kl[g][o + 2]};
                        mma16816(sacc[nf], qh[ks], bhf);
                        mma16816(sacc[nf], qh[ks], blf);
                        mma16816(sacc[nf], ql[ks], bhf);
                    }
                }
                float mx[2] = {-1e30f, -1e30f};
#pragma unroll
                for (int nf = 0; nf < 8; nf++)
#pragma unroll
                    for (int e = 0; e < 4; e++) {
                        const int col = k0 + nf * 8 + (lane & 3) * 2 + (e & 1);
                        const int r = e >> 1;
                        if (col > qi0 + r * 8) sacc[nf][e] = -1e30f;
                        else mx[r] = fmaxf(mx[r], sacc[nf][e]);
                    }
#pragma unroll
                for (int r = 0; r < 2; r++) {
                    mx[r] = fmaxf(mx[r], __shfl_xor_sync(0xffffffffu, mx[r], 1));
                    mx[r] = fmaxf(mx[r], __shfl_xor_sync(0xffffffffu, mx[r], 2));
                }
                float mn[2], corr[2], sum[2] = {0.f, 0.f};
#pragma unroll
                for (int r = 0; r < 2; r++) {
                    mn[r] = fmaxf(mrow[r], mx[r]);
                    corr[r] = __expf(mrow[r] - mn[r]);
                    mrow[r] = mn[r];
                }
#pragma unroll
                for (int nf = 0; nf < 8; nf++)
#pragma unroll
                    for (int e = 0; e < 4; e++) {
                        const int r = e >> 1;
                        const float pv = __expf(sacc[nf][e] - mn[r]);
                        sacc[nf][e] = pv;
                        sum[r] += pv;
                    }
#pragma unroll
                for (int r = 0; r < 2; r++) {
                    sum[r] += __shfl_xor_sync(0xffffffffu, sum[r], 1);
                    sum[r] += __shfl_xor_sync(0xffffffffu, sum[r], 2);
                    lrow[r] = lrow[r] * corr[r] + sum[r];
                }
#pragma unroll
                for (int nf = 0; nf < 8; nf++)
#pragma unroll
                    for (int e = 0; e < 4; e++) oacc[nf][e] *= corr[e >> 1];
#pragma unroll
                for (int ks = 0; ks < 4; ks++) {
                    uint32_t ph[4], pl[4];
                    ph[0] = pack_hi(sacc[2 * ks][0], sacc[2 * ks][1]);
                    pl[0] = pack_lo(sacc[2 * ks][0], sacc[2 * ks][1], ph[0]);
                    ph[1] = pack_hi(sacc[2 * ks][2], sacc[2 * ks][3]);
                    pl[1] = pack_lo(sacc[2 * ks][2], sacc[2 * ks][3], ph[1]);
                    ph[2] = pack_hi(sacc[2 * ks + 1][0], sacc[2 * ks + 1][1]);
                    pl[2] = pack_lo(sacc[2 * ks + 1][0], sacc[2 * ks + 1][1], ph[2]);
                    ph[3] = pack_hi(sacc[2 * ks + 1][2], sacc[2 * ks + 1][3]);
                    pl[3] = pack_lo(sacc[2 * ks + 1][2], sacc[2 * ks + 1][3], ph[3]);
                    uint32_t vh[4][4], vl[4][4];
#pragma unroll
                    for (int g = 0; g < 4; g++) {
                        const uint32_t rb = kvb + 18432 +
                            ((ks * 16 + (lane & 15)) * 72 + g * 16 + (lane >> 4) * 8) * 2;
                        ldm_x4_t(vh[g], rb);
                        ldm_x4_t(vl[g], rb + 9216);
                    }
#pragma unroll
                    for (int nf = 0; nf < 8; nf++) {
                        const int g = nf >> 1, o = (nf & 1) * 2;
                        uint32_t bhf[2] = {vh[g][o], vh[g][o + 1]};
                        uint32_t blf[2] = {vl[g][o], vl[g][o + 1]};
                        mma16816(oacc[nf], ph, bhf);
                        mma16816(oacc[nf], ph, blf);
                        mma16816(oacc[nf], pl, bhf);
                    }
                }
            }
            __syncthreads();
        }

        const int bb = bh >> 3, h = bh & 7;
#pragma unroll
        for (int r = 0; r < 2; r++) {
            const float inv = 1.f / lrow[r];
            const int qi = qi0 + r * 8;
            const size_t rowoff = ((size_t)bb * SEQ + qi) * DMODEL + h * HDIM;
#pragma unroll
            for (int nf = 0; nf < 8; nf++) {
                const int hd = nf * 8 + (lane & 3) * 2;
                const float v0 = oacc[nf][r * 2] * inv;
                const float v1 = oacc[nf][r * 2 + 1] * inv;
                const uint32_t hv = pack_hi(v0, v1);
                *reinterpret_cast<uint32_t*>(g_aoh + rowoff + hd) = hv;
                *reinterpret_cast<uint32_t*>(g_aol + rowoff + hd) = pack_lo(v0, v1, hv);
            }
        }
    }
}

// ---------------------------------------------------------------- launch
extern "C" void kernel_launch(void* const* d_in, const int* in_sizes, int n_in,
                              void* d_out, int out_size) {
    const float* x     = (const float*)d_in[0];
    const float* w_qkv = (const float*)d_in[1];
    const float* b_qkv = (const float*)d_in[2];
    const float* w_out = (const float*)d_in[3];
    const float* b_out = (const float*)d_in[4];
    float* out = (float*)d_out;

    bf16 *xh, *xl, *wqh, *wql, *woh, *wol, *aoh, *aol;
    cudaGetSymbolAddress((void**)&xh, g_xh);   cudaGetSymbolAddress((void**)&xl, g_xl);
    cudaGetSymbolAddress((void**)&wqh, g_wqh); cudaGetSymbolAddress((void**)&wql, g_wql);
    cudaGetSymbolAddress((void**)&woh, g_woh); cudaGetSymbolAddress((void**)&wol, g_wol);
    cudaGetSymbolAddress((void**)&aoh, g_aoh); cudaGetSymbolAddress((void**)&aol, g_aol);

    const int SMEM_GEMM = 3 * GSTG;      // 89088
    const int SMEM_ATT  = 110592;
    cudaFuncSetAttribute(gemm_mma<0>, cudaFuncAttributeMaxDynamicSharedMemorySize, SMEM_GEMM);
    cudaFuncSetAttribute(gemm_mma<1>, cudaFuncAttributeMaxDynamicSharedMemorySize, SMEM_GEMM);
    cudaFuncSetAttribute(attn_mma,    cudaFuncAttributeMaxDynamicSharedMemorySize, SMEM_ATT);

    convert_k<<<(MROWS * DMODEL / 4 + 255) / 256, 256>>>(
        (const float4*)x, (uint2*)xh, (uint2*)xl, MROWS * DMODEL / 4);
    convert_k<<<(DMODEL * QKV_N / 4 + 255) / 256, 256>>>(
        (const float4*)w_qkv, (uint2*)wqh, (uint2*)wql, DMODEL * QKV_N / 4);
    convert_k<<<(DMODEL * DMODEL / 4 + 255) / 256, 256>>>(
        (const float4*)w_out, (uint2*)woh, (uint2*)wol, DMODEL * DMODEL / 4);

    // 1) QKV projection -> q/k/v bf16 hi/lo (Q pre-scaled)
    gemm_mma<0><<<dim3(QKV_N / 64, MROWS / 128), 256, SMEM_GEMM>>>(
        xh, xl, wqh, wql, b_qkv, nullptr, QKV_N);
    // 2) causal attention (single balanced wave) -> g_aoh/g_aol
    attn_mma<<<dim3(4, BATCH * NHEAD), 256, SMEM_ATT>>>();
    // 3) output projection -> fp32 out
    gemm_mma<1><<<dim3(DMODEL / 64, MROWS / 128), 256, SMEM_GEMM>>>(
        aoh, aol, woh, wol, b_out, out, DMODEL);
}

// round 8
// speedup vs baseline: 1.2864x; 1.0986x over previous
#include <cuda_runtime.h>
#include <cuda_bf16.h>
#include <cstdint>

// ---------------------------------------------------------------- constants
#define BATCH 4
#define SEQ   2048
#define DMODEL 512
#define NHEAD 8
#define HDIM  64
#define MROWS 8192
#define QKV_N 1536

typedef __nv_bfloat16 bf16;

// ---------------------------------------------------------------- scratch
__device__ bf16 g_xh[(size_t)MROWS * DMODEL];
__device__ bf16 g_xl[(size_t)MROWS * DMODEL];
__device__ bf16 g_wqh[(size_t)DMODEL * QKV_N];
__device__ bf16 g_wql[(size_t)DMODEL * QKV_N];
__device__ bf16 g_woh[(size_t)DMODEL * DMODEL];
__device__ bf16 g_wol[(size_t)DMODEL * DMODEL];
__device__ bf16 g_qh[(size_t)BATCH * NHEAD * SEQ * HDIM];
__device__ bf16 g_ql[(size_t)BATCH * NHEAD * SEQ * HDIM];
__device__ bf16 g_kh[(size_t)BATCH * NHEAD * SEQ * HDIM];
__device__ bf16 g_kl[(size_t)BATCH * NHEAD * SEQ * HDIM];
__device__ bf16 g_vh[(size_t)BATCH * NHEAD * SEQ * HDIM];
__device__ bf16 g_vl[(size_t)BATCH * NHEAD * SEQ * HDIM];
__device__ bf16 g_aoh[(size_t)MROWS * DMODEL];
__device__ bf16 g_aol[(size_t)MROWS * DMODEL];

// ---------------------------------------------------------------- helpers
__device__ __forceinline__ uint32_t smem_u32(const void* p) {
    uint32_t a;
    asm("{ .reg .u64 t; cvta.to.shared.u64 t, %1; cvt.u32.u64 %0, t; }"
        : "=r"(a) : "l"(p));
    return a;
}
__device__ __forceinline__ void ldm_x4(uint32_t* r, uint32_t addr) {
    asm volatile("ldmatrix.sync.aligned.m8n8.x4.shared.b16 {%0,%1,%2,%3}, [%4];"
                 : "=r"(r[0]), "=r"(r[1]), "=r"(r[2]), "=r"(r[3]) : "r"(addr));
}
__device__ __forceinline__ void ldm_x4_t(uint32_t* r, uint32_t addr) {
    asm volatile("ldmatrix.sync.aligned.m8n8.x4.trans.shared.b16 {%0,%1,%2,%3}, [%4];"
                 : "=r"(r[0]), "=r"(r[1]), "=r"(r[2]), "=r"(r[3]) : "r"(addr));
}
__device__ __forceinline__ void mma16816(float* d, const uint32_t* a, const uint32_t* b) {
    asm volatile(
        "mma.sync.aligned.m16n8k16.row.col.f32.bf16.bf16.f32 "
        "{%0,%1,%2,%3}, {%4,%5,%6,%7}, {%8,%9}, {%0,%1,%2,%3};"
        : "+f"(d[0]), "+f"(d[1]), "+f"(d[2]), "+f"(d[3])
        : "r"(a[0]), "r"(a[1]), "r"(a[2]), "r"(a[3]), "r"(b[0]), "r"(b[1]));
}
__device__ __forceinline__ uint32_t pack_hi(float a, float b) {
    __nv_bfloat162 h = __floats2bfloat162_rn(a, b);
    return *reinterpret_cast<uint32_t*>(&h);
}
__device__ __forceinline__ uint32_t pack_lo(float a, float b, uint32_t hi) {
    __nv_bfloat162 h = *reinterpret_cast<__nv_bfloat162*>(&hi);
    float la = a - __bfloat162float(h.x);
    float lb = b - __bfloat162float(h.y);
    __nv_bfloat162 l = __floats2bfloat162_rn(la, lb);
    return *reinterpret_cast<uint32_t*>(&l);
}

#define CP16(dst, src) \
    asm volatile("cp.async.cg.shared.global [%0], [%1], 16;" :: "r"(dst), "l"(src))
#define CP_COMMIT() asm volatile("cp.async.commit_group;" ::: "memory")
#define CP_WAIT(n)  asm volatile("cp.async.wait_group %0;" :: "n"(n) : "memory")

// ---------------------------------------------------------------- convert
__global__ __launch_bounds__(256)
void convert_k(const float4* __restrict__ src, uint2* __restrict__ hi,
               uint2* __restrict__ lo, int n4) {
    const int i = blockIdx.x * 256 + threadIdx.x;
    if (i < n4) {
        float4 v = src[i];
        uint2 h, l;
        h.x = pack_hi(v.x, v.y); l.x = pack_lo(v.x, v.y, h.x);
        h.y = pack_hi(v.z, v.w); l.y = pack_lo(v.z, v.w, h.y);
        hi[i] = h; lo[i] = l;
    }
}

// ---------------------------------------------------------------- GEMM (HMMA, bf16 in)
// C[M,N] = A[M,512] @ W[512,N] (+bias). BM=128 BN=64 BK=32, 8 warps (4m x 2n),
// warp tile 32x32. 3-stage cp.async pipeline, 2 CTAs/SM.
// Stage (29696 B): AH[128x40]@0, AL@10240, BH[32x72]@20480, BL@25088.
#define GSTG 29696
template <int MODE>
__global__ __launch_bounds__(256, 2)
void gemm_mma(const bf16* __restrict__ Ah, const bf16* __restrict__ Al,
              const bf16* __restrict__ Bh, const bf16* __restrict__ Bl,
              const float* __restrict__ bias, float* __restrict__ C, int N) {
    extern __shared__ char sm[];
    const uint32_t sbase = smem_u32(sm);
    const int tid = threadIdx.x, lane = tid & 31, w = tid >> 5;
    const int wm = w >> 1, wn = w & 1;
    const int m0 = blockIdx.y * 128, n0 = blockIdx.x * 64;

    float acc[2][4][4];
#pragma unroll
    for (int i = 0; i < 2; i++)
#pragma unroll
        for (int j = 0; j < 4; j++)
#pragma unroll
            for (int e = 0; e < 4; e++) acc[i][j][e] = 0.f;

    const int aq0 = tid * 2;
    const int ar0 = aq0 >> 2, ac0 = aq0 & 3;
    const int ar1 = (aq0 + 1) >> 2, ac1 = (aq0 + 1) & 3;
    const int br = tid >> 3, bc = tid & 7;

    auto issue = [&](int kt) {
        const uint32_t base = sbase + (kt % 3) * GSTG;
        const size_t a0 = (size_t)(m0 + ar0) * 512 + kt * 32 + ac0 * 8;
        const size_t a1 = (size_t)(m0 + ar1) * 512 + kt * 32 + ac1 * 8;
        CP16(base + ar0 * 80 + ac0 * 16, Ah + a0);
        CP16(base + ar1 * 80 + ac1 * 16, Ah + a1);
        CP16(base + 10240 + ar0 * 80 + ac0 * 16, Al + a0);
        CP16(base + 10240 + ar1 * 80 + ac1 * 16, Al + a1);
        const size_t b0 = (size_t)(kt * 32 + br) * N + n0 + bc * 8;
        CP16(base + 20480 + br * 144 + bc * 16, Bh + b0);
        CP16(base + 25088 + br * 144 + bc * 16, Bl + b0);
        CP_COMMIT();
    };

    issue(0);
    issue(1);
    for (int kt = 0; kt < 16; kt++) {
        CP_WAIT(1);
        __syncthreads();
        if (kt + 2 < 16) issue(kt + 2);
        const uint32_t bA = sbase + (kt % 3) * GSTG;
#pragma unroll
        for (int ks = 0; ks < 2; ks++) {
            uint32_t ah[2][4], al[2][4];
#pragma unroll
            for (int mf = 0; mf < 2; mf++) {
                const uint32_t ra = bA +
                    ((wm * 32 + mf * 16 + (lane & 15)) * 40 + ks * 16 + (lane >> 4) * 8) * 2;
                ldm_x4(ah[mf], ra);
                ldm_x4(al[mf], ra + 10240);
            }
            uint32_t bh[2][4], bl[2][4];
#pragma unroll
            for (int g = 0; g < 2; g++) {
                const uint32_t rb = bA + 20480 +
                    ((ks * 16 + (lane & 15)) * 72 + wn * 32 + g * 16 + (lane >> 4) * 8) * 2;
                ldm_x4_t(bh[g], rb);
                ldm_x4_t(bl[g], rb + 4608);
            }
#pragma unroll
            for (int mf = 0; mf < 2; mf++)
#pragma unroll
                for (int nf = 0; nf < 4; nf++) {
                    const int g = nf >> 1, o = (nf & 1) * 2;
                    uint32_t bhf[2] = {bh[g][o], bh[g][o + 1]};
                    uint32_t blf[2] = {bl[g][o], bl[g][o + 1]};
                    mma16816(acc[mf][nf], ah[mf], bhf);
                    mma16816(acc[mf][nf], ah[mf], blf);
                    mma16816(acc[mf][nf], al[mf], bhf);
                }
        }
    }

    // epilogue
#pragma unroll
    for (int mf = 0; mf < 2; mf++)
#pragma unroll
        for (int nf = 0; nf < 4; nf++) {
            const int col = n0 + wn * 32 + nf * 8 + (lane & 3) * 2;
            const float b0 = bias[col], b1 = bias[col + 1];
#pragma unroll
            for (int rr = 0; rr < 2; rr++) {
                const int row = m0 + wm * 32 + mf * 16 + (lane >> 2) + rr * 8;
                float v0 = acc[mf][nf][rr * 2] + b0;
                float v1 = acc[mf][nf][rr * 2 + 1] + b1;
                if (MODE == 0) {
                    const int part = col >> 9, ww = col & 511;
                    const int h = ww >> 6, hd = ww & 63;
                    const int bb = row >> 11, sidx = row & 2047;
                    if (part == 0) { v0 *= 0.125f; v1 *= 0.125f; }
                    bf16* dh = (part == 0) ? g_qh : (part == 1) ? g_kh : g_vh;
                    bf16* dl = (part == 0) ? g_ql : (part == 1) ? g_kl : g_vl;
                    const size_t idx =
                        ((((size_t)bb * NHEAD + h) * SEQ) + sidx) * HDIM + hd;
                    const uint32_t hv = pack_hi(v0, v1);
                    *reinterpret_cast<uint32_t*>(dh + idx) = hv;
                    *reinterpret_cast<uint32_t*>(dl + idx) = pack_lo(v0, v1, hv);
                } else {
                    *reinterpret_cast<float2*>(C + (size_t)row * N + col) =
                        make_float2(v0, v1);
                }
            }
        }
}

// ---------------------------------------------------------------- attention (HMMA, bf16 in)
// 512 threads (16 warps), q-block = 256 rows, grid (4, 32): CTA p handles
// q-blocks {p, 7-p} -> exactly 36 k-block iterations per CTA, one wave.
// Warp owns 16 q-rows; Q re-loaded from smem per ks (saves 32 regs/thread).
// Smem: QH@0, QL@36864 (256 rows x 72); KV stage s @ 73728+s*36864:
//   KH@+0, KL@+9216, VH@+18432, VL@+27648 (64 rows x 72 each). Total 147456 B.
__global__ __launch_bounds__(512)
void attn_mma() {
    extern __shared__ char sm[];
    const uint32_t sbase = smem_u32(sm);
    const int tid = threadIdx.x, lane = tid & 31, w = tid >> 5;
    const int p = blockIdx.x, bh = blockIdx.y;

    const size_t hbase = (size_t)bh * SEQ * HDIM;
    const int qlist[2] = {p, 7 - p};

    auto issueKV = [&](int kb, int buf) {
        const uint32_t base = sbase + 73728 + buf * 36864;
        const int k0 = kb * 64;
        const bf16* srcs[4] = {g_kh + hbase, g_kl + hbase, g_vh + hbase, g_vl + hbase};
        const int row = tid >> 3, c = tid & 7;
#pragma unroll
        for (int a = 0; a < 4; a++) {
            CP16(base + a * 9216 + row * 144 + c * 16,
                 srcs[a] + (size_t)(k0 + row) * 64 + c * 8);
        }
        CP_COMMIT();
    };

    for (int qq = 0; qq < 2; qq++) {
        const int qb = qlist[qq];
        const bf16* Qh = g_qh + hbase + (size_t)qb * 256 * HDIM;
        const bf16* Ql = g_ql + hbase + (size_t)qb * 256 * HDIM;

        // issue Q (256 rows x 64, hi+lo)
#pragma unroll
        for (int t = 0; t < 4; t++) {
            const int q = tid * 4 + t;
            const int row = q >> 3, c = q & 7;
            const size_t so = (size_t)row * 64 + c * 8;
            CP16(sbase + row * 144 + c * 16, Qh + so);
            CP16(sbase + 36864 + row * 144 + c * 16, Ql + so);
        }
        CP_COMMIT();

        const int nkb = 4 * qb + 4;
        issueKV(0, 0);
        CP_WAIT(1);  // Q + KV stage 0 ready
        __syncthreads();

        float oacc[8][4];
#pragma unroll
        for (int j = 0; j < 8; j++)
#pragma unroll
            for (int e = 0; e < 4; e++) oacc[j][e] = 0.f;
        float mrow[2] = {-1e30f, -1e30f};
        float lrow[2] = {0.f, 0.f};
        const int qi0 = qb * 256 + w * 16 + (lane >> 2);

        for (int kb = 0; kb < nkb; kb++) {
            const int k0 = kb * 64;
            if (kb + 1 < nkb) { issueKV(kb + 1, (kb + 1) & 1); CP_WAIT(1); }
            else CP_WAIT(0);
            __syncthreads();
            const uint32_t kvb = sbase + 73728 + (kb & 1) * 36864;

            if (qb * 256 + w * 16 + 15 >= k0) {
                // ---- S = Q K^T
                float sacc[8][4];
#pragma unroll
                for (int j = 0; j < 8; j++)
#pragma unroll
                    for (int e = 0; e < 4; e++) sacc[j][e] = 0.f;
#pragma unroll
                for (int ks = 0; ks < 4; ks++) {
                    uint32_t qhf[4], qlf[4];
                    const uint32_t ra = sbase +
                        ((w * 16 + (lane & 15)) * 72 + ks * 16 + (lane >> 4) * 8) * 2;
                    ldm_x4(qhf, ra);
                    ldm_x4(qlf, ra + 36864);
                    uint32_t kh[4][4], kl[4][4];
#pragma unroll
                    for (int g = 0; g < 4; g++) {
                        const uint32_t rb = kvb +
                            ((g * 16 + (lane & 15)) * 72 + ks * 16 + (lane >> 4) * 8) * 2;
                        ldm_x4(kh[g], rb);
                        ldm_x4(kl[g], rb + 9216);
                    }
#pragma unroll
                    for (int nf = 0; nf < 8; nf++) {
                        const int g = nf >> 1, o = nf & 1;
                        uint32_t bhf[2] = {kh[g][o], kh[g][o + 2]};
                        uint32_t blf[2] = {kl[g][o], kl[g][o + 2]};
                        mma16816(sacc[nf], qhf, bhf);
                        mma16816(sacc[nf], qhf, blf);
                        mma16816(sacc[nf], qlf, bhf);
                    }
                }
                // ---- online softmax
                float mx[2] = {-1e30f, -1e30f};
#pragma unroll
                for (int nf = 0; nf < 8; nf++)
#pragma unroll
                    for (int e = 0; e < 4; e++) {
                        const int col = k0 + nf * 8 + (lane & 3) * 2 + (e & 1);
                        const int r = e >> 1;
                        if (col > qi0 + r * 8) sacc[nf][e] = -1e30f;
                        else mx[r] = fmaxf(mx[r], sacc[nf][e]);
                    }
#pragma unroll
                for (int r = 0; r < 2; r++) {
                    mx[r] = fmaxf(mx[r], __shfl_xor_sync(0xffffffffu, mx[r], 1));
                    mx[r] = fmaxf(mx[r], __shfl_xor_sync(0xffffffffu, mx[r], 2));
                }
                float mn[2], corr[2], sum[2] = {0.f, 0.f};
#pragma unroll
                for (int r = 0; r < 2; r++) {
                    mn[r] = fmaxf(mrow[r], mx[r]);
                    corr[r] = __expf(mrow[r] - mn[r]);
                    mrow[r] = mn[r];
                }
#pragma unroll
                for (int nf = 0; nf < 8; nf++)
#pragma unroll
                    for (int e = 0; e < 4; e++) {
                        const int r = e >> 1;
                        const float pv = __expf(sacc[nf][e] - mn[r]);
                        sacc[nf][e] = pv;
                        sum[r] += pv;
                    }
#pragma unroll
                for (int r = 0; r < 2; r++) {
                    sum[r] += __shfl_xor_sync(0xffffffffu, sum[r], 1);
                    sum[r] += __shfl_xor_sync(0xffffffffu, sum[r], 2);
                    lrow[r] = lrow[r] * corr[r] + sum[r];
                }
#pragma unroll
                for (int nf = 0; nf < 8; nf++)
#pragma unroll
                    for (int e = 0; e < 4; e++) oacc[nf][e] *= corr[e >> 1];
                // ---- PV
#pragma unroll
                for (int ks = 0; ks < 4; ks++) {
                    uint32_t ph[4], pl[4];
                    ph[0] = pack_hi(sacc[2 * ks][0], sacc[2 * ks][1]);
                    pl[0] = pack_lo(sacc[2 * ks][0], sacc[2 * ks][1], ph[0]);
                    ph[1] = pack_hi(sacc[2 * ks][2], sacc[2 * ks][3]);
                    pl[1] = pack_lo(sacc[2 * ks][2], sacc[2 * ks][3], ph[1]);
                    ph[2] = pack_hi(sacc[2 * ks + 1][0], sacc[2 * ks + 1][1]);
                    pl[2] = pack_lo(sacc[2 * ks + 1][0], sacc[2 * ks + 1][1], ph[2]);
                    ph[3] = pack_hi(sacc[2 * ks + 1][2], sacc[2 * ks + 1][3]);
                    pl[3] = pack_lo(sacc[2 * ks + 1][2], sacc[2 * ks + 1][3], ph[3]);
                    uint32_t vh[4][4], vl[4][4];
#pragma unroll
                    for (int g = 0; g < 4; g++) {
                        const uint32_t rb = kvb + 18432 +
                            ((ks * 16 + (lane & 15)) * 72 + g * 16 + (lane >> 4) * 8) * 2;
                        ldm_x4_t(vh[g], rb);
                        ldm_x4_t(vl[g], rb + 9216);
                    }
#pragma unroll
                    for (int nf = 0; nf < 8; nf++) {
                        const int g = nf >> 1, o = (nf & 1) * 2;
                        uint32_t bhf[2] = {vh[g][o], vh[g][o + 1]};
                        uint32_t blf[2] = {vl[g][o], vl[g][o + 1]};
                        mma16816(oacc[nf], ph, bhf);
                        mma16816(oacc[nf], ph, blf);
                        mma16816(oacc[nf], pl, bhf);
                    }
                }
            }
            __syncthreads();
        }

        // write out as bf16 hi/lo (input of out-proj GEMM)
        const int bb = bh >> 3, h = bh & 7;
#pragma unroll
        for (int r = 0; r < 2; r++) {
            const float inv = 1.f / lrow[r];
            const int qi = qi0 + r * 8;
            const size_t rowoff = ((size_t)bb * SEQ + qi) * DMODEL + h * HDIM;
#pragma unroll
            for (int nf = 0; nf < 8; nf++) {
                const int hd = nf * 8 + (lane & 3) * 2;
                const float v0 = oacc[nf][r * 2] * inv;
                const float v1 = oacc[nf][r * 2 + 1] * inv;
                const uint32_t hv = pack_hi(v0, v1);
                *reinterpret_cast<uint32_t*>(g_aoh + rowoff + hd) = hv;
                *reinterpret_cast<uint32_t*>(g_aol + rowoff + hd) = pack_lo(v0, v1, hv);
            }
        }
    }
}

// ---------------------------------------------------------------- launch
extern "C" void kernel_launch(void* const* d_in, const int* in_sizes, int n_in,
                              void* d_out, int out_size) {
    const float* x     = (const float*)d_in[0];
    const float* w_qkv = (const float*)d_in[1];
    const float* b_qkv = (const float*)d_in[2];
    const float* w_out = (const float*)d_in[3];
    const float* b_out = (const float*)d_in[4];
    float* out = (float*)d_out;

    bf16 *xh, *xl, *wqh, *wql, *woh, *wol, *aoh, *aol;
    cudaGetSymbolAddress((void**)&xh, g_xh);   cudaGetSymbolAddress((void**)&xl, g_xl);
    cudaGetSymbolAddress((void**)&wqh, g_wqh); cudaGetSymbolAddress((void**)&wql, g_wql);
    cudaGetSymbolAddress((void**)&woh, g_woh); cudaGetSymbolAddress((void**)&wol, g_wol);
    cudaGetSymbolAddress((void**)&aoh, g_aoh); cudaGetSymbolAddress((void**)&aol, g_aol);

    const int SMEM_GEMM = 3 * GSTG;      // 89088
    const int SMEM_ATT  = 147456;
    cudaFuncSetAttribute(gemm_mma<0>, cudaFuncAttributeMaxDynamicSharedMemorySize, SMEM_GEMM);
    cudaFuncSetAttribute(gemm_mma<1>, cudaFuncAttributeMaxDynamicSharedMemorySize, SMEM_GEMM);
    cudaFuncSetAttribute(attn_mma,    cudaFuncAttributeMaxDynamicSharedMemorySize, SMEM_ATT);

    convert_k<<<(MROWS * DMODEL / 4 + 255) / 256, 256>>>(
        (const float4*)x, (uint2*)xh, (uint2*)xl, MROWS * DMODEL / 4);
    convert_k<<<(DMODEL * QKV_N / 4 + 255) / 256, 256>>>(
        (const float4*)w_qkv, (uint2*)wqh, (uint2*)wql, DMODEL * QKV_N / 4);
    convert_k<<<(DMODEL * DMODEL / 4 + 255) / 256, 256>>>(
        (const float4*)w_out, (uint2*)woh, (uint2*)wol, DMODEL * DMODEL / 4);

    // 1) QKV projection -> q/k/v bf16 hi/lo (Q pre-scaled)
    gemm_mma<0><<<dim3(QKV_N / 64, MROWS / 128), 256, SMEM_GEMM>>>(
        xh, xl, wqh, wql, b_qkv, nullptr, QKV_N);
    // 2) causal attention (single balanced wave, 512 threads) -> g_aoh/g_aol
    attn_mma<<<dim3(4, BATCH * NHEAD), 512, SMEM_ATT>>>();
    // 3) output projection -> fp32 out
    gemm_mma<1><<<dim3(DMODEL / 64, MROWS / 128), 256, SMEM_GEMM>>>(
        aoh, aol, woh, wol, b_out, out, DMODEL);
}

// round 9
// speedup vs baseline: 1.7025x; 1.3235x over previous
#include <cuda_runtime.h>
#include <cuda_bf16.h>
#include <cuda_fp16.h>
#include <cstdint>

// ---------------------------------------------------------------- constants
#define BATCH 4
#define SEQ   2048
#define DMODEL 512
#define NHEAD 8
#define HDIM  64
#define MROWS 8192
#define QKV_N 1536

typedef __nv_bfloat16 bf16;

// ---------------------------------------------------------------- scratch
__device__ bf16 g_xh[(size_t)MROWS * DMODEL];
__device__ bf16 g_xl[(size_t)MROWS * DMODEL];
__device__ bf16 g_wqh[(size_t)DMODEL * QKV_N];
__device__ bf16 g_wql[(size_t)DMODEL * QKV_N];
__device__ bf16 g_woh[(size_t)DMODEL * DMODEL];
__device__ bf16 g_wol[(size_t)DMODEL * DMODEL];
__device__ __half g_qf[(size_t)BATCH * NHEAD * SEQ * HDIM];
__device__ __half g_kf[(size_t)BATCH * NHEAD * SEQ * HDIM];
__device__ __half g_vf[(size_t)BATCH * NHEAD * SEQ * HDIM];
__device__ bf16 g_aoh[(size_t)MROWS * DMODEL];
__device__ bf16 g_aol[(size_t)MROWS * DMODEL];

// ---------------------------------------------------------------- helpers
__device__ __forceinline__ uint32_t smem_u32(const void* p) {
    uint32_t a;
    asm("{ .reg .u64 t; cvta.to.shared.u64 t, %1; cvt.u32.u64 %0, t; }"
        : "=r"(a) : "l"(p));
    return a;
}
__device__ __forceinline__ void ldm_x4(uint32_t* r, uint32_t addr) {
    asm volatile("ldmatrix.sync.aligned.m8n8.x4.shared.b16 {%0,%1,%2,%3}, [%4];"
                 : "=r"(r[0]), "=r"(r[1]), "=r"(r[2]), "=r"(r[3]) : "r"(addr));
}
__device__ __forceinline__ void ldm_x4_t(uint32_t* r, uint32_t addr) {
    asm volatile("ldmatrix.sync.aligned.m8n8.x4.trans.shared.b16 {%0,%1,%2,%3}, [%4];"
                 : "=r"(r[0]), "=r"(r[1]), "=r"(r[2]), "=r"(r[3]) : "r"(addr));
}
__device__ __forceinline__ void mma16816(float* d, const uint32_t* a, const uint32_t* b) {
    asm volatile(
        "mma.sync.aligned.m16n8k16.row.col.f32.bf16.bf16.f32 "
        "{%0,%1,%2,%3}, {%4,%5,%6,%7}, {%8,%9}, {%0,%1,%2,%3};"
        : "+f"(d[0]), "+f"(d[1]), "+f"(d[2]), "+f"(d[3])
        : "r"(a[0]), "r"(a[1]), "r"(a[2]), "r"(a[3]), "r"(b[0]), "r"(b[1]));
}
__device__ __forceinline__ void mma16816h(float* d, const uint32_t* a, const uint32_t* b) {
    asm volatile(
        "mma.sync.aligned.m16n8k16.row.col.f32.f16.f16.f32 "
        "{%0,%1,%2,%3}, {%4,%5,%6,%7}, {%8,%9}, {%0,%1,%2,%3};"
        : "+f"(d[0]), "+f"(d[1]), "+f"(d[2]), "+f"(d[3])
        : "r"(a[0]), "r"(a[1]), "r"(a[2]), "r"(a[3]), "r"(b[0]), "r"(b[1]));
}
__device__ __forceinline__ uint32_t pack_hi(float a, float b) {
    __nv_bfloat162 h = __floats2bfloat162_rn(a, b);
    return *reinterpret_cast<uint32_t*>(&h);
}
__device__ __forceinline__ uint32_t pack_lo(float a, float b, uint32_t hi) {
    __nv_bfloat162 h = *reinterpret_cast<__nv_bfloat162*>(&hi);
    float la = a - __bfloat162float(h.x);
    float lb = b - __bfloat162float(h.y);
    __nv_bfloat162 l = __floats2bfloat162_rn(la, lb);
    return *reinterpret_cast<uint32_t*>(&l);
}
__device__ __forceinline__ uint32_t pack_f16(float a, float b) {
    __half2 h = __floats2half2_rn(a, b);
    return *reinterpret_cast<uint32_t*>(&h);
}

#define CP16(dst, src) \
    asm volatile("cp.async.cg.shared.global [%0], [%1], 16;" :: "r"(dst), "l"(src))
#define CP_COMMIT() asm volatile("cp.async.commit_group;" ::: "memory")
#define CP_WAIT(n)  asm volatile("cp.async.wait_group %0;" :: "n"(n) : "memory")

// ---------------------------------------------------------------- convert
__global__ __launch_bounds__(256)
void convert_k(const float4* __restrict__ src, uint2* __restrict__ hi,
               uint2* __restrict__ lo, int n4) {
    const int i = blockIdx.x * 256 + threadIdx.x;
    if (i < n4) {
        float4 v = src[i];
        uint2 h, l;
        h.x = pack_hi(v.x, v.y); l.x = pack_lo(v.x, v.y, h.x);
        h.y = pack_hi(v.z, v.w); l.y = pack_lo(v.z, v.w, h.y);
        hi[i] = h; lo[i] = l;
    }
}

// ---------------------------------------------------------------- GEMM (HMMA, bf16 in)
// C[M,N] = A[M,512] @ W[512,N] (+bias). BM=128 BN=64 BK=32, 8 warps (4m x 2n),
// warp tile 32x32. 3-stage cp.async pipeline, 2 CTAs/SM.
// Stage (29696 B): AH[128x40]@0, AL@10240, BH[32x72]@20480, BL@25088.
#define GSTG 29696
template <int MODE>
__global__ __launch_bounds__(256, 2)
void gemm_mma(const bf16* __restrict__ Ah, const bf16* __restrict__ Al,
              const bf16* __restrict__ Bh, const bf16* __restrict__ Bl,
              const float* __restrict__ bias, float* __restrict__ C, int N) {
    extern __shared__ char sm[];
    const uint32_t sbase = smem_u32(sm);
    const int tid = threadIdx.x, lane = tid & 31, w = tid >> 5;
    const int wm = w >> 1, wn = w & 1;
    const int m0 = blockIdx.y * 128, n0 = blockIdx.x * 64;

    float acc[2][4][4];
#pragma unroll
    for (int i = 0; i < 2; i++)
#pragma unroll
        for (int j = 0; j < 4; j++)
#pragma unroll
            for (int e = 0; e < 4; e++) acc[i][j][e] = 0.f;

    const int aq0 = tid * 2;
    const int ar0 = aq0 >> 2, ac0 = aq0 & 3;
    const int ar1 = (aq0 + 1) >> 2, ac1 = (aq0 + 1) & 3;
    const int br = tid >> 3, bc = tid & 7;

    auto issue = [&](int kt) {
        const uint32_t base = sbase + (kt % 3) * GSTG;
        const size_t a0 = (size_t)(m0 + ar0) * 512 + kt * 32 + ac0 * 8;
        const size_t a1 = (size_t)(m0 + ar1) * 512 + kt * 32 + ac1 * 8;
        CP16(base + ar0 * 80 + ac0 * 16, Ah + a0);
        CP16(base + ar1 * 80 + ac1 * 16, Ah + a1);
        CP16(base + 10240 + ar0 * 80 + ac0 * 16, Al + a0);
        CP16(base + 10240 + ar1 * 80 + ac1 * 16, Al + a1);
        const size_t b0 = (size_t)(kt * 32 + br) * N + n0 + bc * 8;
        CP16(base + 20480 + br * 144 + bc * 16, Bh + b0);
        CP16(base + 25088 + br * 144 + bc * 16, Bl + b0);
        CP_COMMIT();
    };

    issue(0);
    issue(1);
    for (int kt = 0; kt < 16; kt++) {
        CP_WAIT(1);
        __syncthreads();
        if (kt + 2 < 16) issue(kt + 2);
        const uint32_t bA = sbase + (kt % 3) * GSTG;
#pragma unroll
        for (int ks = 0; ks < 2; ks++) {
            uint32_t ah[2][4], al[2][4];
#pragma unroll
            for (int mf = 0; mf < 2; mf++) {
                const uint32_t ra = bA +
                    ((wm * 32 + mf * 16 + (lane & 15)) * 40 + ks * 16 + (lane >> 4) * 8) * 2;
                ldm_x4(ah[mf], ra);
                ldm_x4(al[mf], ra + 10240);
            }
            uint32_t bh[2][4], bl[2][4];
#pragma unroll
            for (int g = 0; g < 2; g++) {
                const uint32_t rb = bA + 20480 +
                    ((ks * 16 + (lane & 15)) * 72 + wn * 32 + g * 16 + (lane >> 4) * 8) * 2;
                ldm_x4_t(bh[g], rb);
                ldm_x4_t(bl[g], rb + 4608);
            }
#pragma unroll
            for (int mf = 0; mf < 2; mf++)
#pragma unroll
                for (int nf = 0; nf < 4; nf++) {
                    const int g = nf >> 1, o = (nf & 1) * 2;
                    uint32_t bhf[2] = {bh[g][o], bh[g][o + 1]};
                    uint32_t blf[2] = {bl[g][o], bl[g][o + 1]};
                    mma16816(acc[mf][nf], ah[mf], bhf);
                    mma16816(acc[mf][nf], ah[mf], blf);
                    mma16816(acc[mf][nf], al[mf], bhf);
                }
        }
    }

    // epilogue
#pragma unroll
    for (int mf = 0; mf < 2; mf++)
#pragma unroll
        for (int nf = 0; nf < 4; nf++) {
            const int col = n0 + wn * 32 + nf * 8 + (lane & 3) * 2;
            const float b0 = bias[col], b1 = bias[col + 1];
#pragma unroll
            for (int rr = 0; rr < 2; rr++) {
                const int row = m0 + wm * 32 + mf * 16 + (lane >> 2) + rr * 8;
                float v0 = acc[mf][nf][rr * 2] + b0;
                float v1 = acc[mf][nf][rr * 2 + 1] + b1;
                if (MODE == 0) {
                    const int part = col >> 9, ww = col & 511;
                    const int h = ww >> 6, hd = ww & 63;
                    const int bb = row >> 11, sidx = row & 2047;
                    if (part == 0) { v0 *= 0.125f; v1 *= 0.125f; }
                    __half* df = (part == 0) ? g_qf : (part == 1) ? g_kf : g_vf;
                    const size_t idx =
                        ((((size_t)bb * NHEAD + h) * SEQ) + sidx) * HDIM + hd;
                    *reinterpret_cast<uint32_t*>(df + idx) = pack_f16(v0, v1);
                } else {
                    *reinterpret_cast<float2*>(C + (size_t)row * N + col) =
                        make_float2(v0, v1);
                }
            }
        }
}

// ---------------------------------------------------------------- attention (fp16 HMMA)
// 512 threads (16 warps), q-block = 256 rows, grid (4, 32): CTA p handles
// q-blocks {p, 7-p} -> exactly 36 k-block iterations per CTA, one wave.
// Single-pass fp16 MMA for S and PV (error budget analysis: ~3e-4 final).
// Smem: Q@0 (256x72 halfs, 36864 B); KV stage s @ 36864+s*18432:
//   K@+0 (64x72x2 = 9216 B), V@+9216. Total 73728 B.
__global__ __launch_bounds__(512)
void attn_mma() {
    extern __shared__ char sm[];
    const uint32_t sbase = smem_u32(sm);
    const int tid = threadIdx.x, lane = tid & 31, w = tid >> 5;
    const int p = blockIdx.x, bh = blockIdx.y;

    const size_t hbase = (size_t)bh * SEQ * HDIM;
    const int qlist[2] = {p, 7 - p};

    auto issueKV = [&](int kb, int buf) {
        const uint32_t base = sbase + 36864 + buf * 18432;
        const int k0 = kb * 64;
        const int row = tid >> 3, c = tid & 7;
        CP16(base + row * 144 + c * 16, g_kf + hbase + (size_t)(k0 + row) * 64 + c * 8);
        CP16(base + 9216 + row * 144 + c * 16, g_vf + hbase + (size_t)(k0 + row) * 64 + c * 8);
        CP_COMMIT();
    };

    for (int qq = 0; qq < 2; qq++) {
        const int qb = qlist[qq];
        const __half* Qf = g_qf + hbase + (size_t)qb * 256 * HDIM;

        // issue Q (256 rows x 64 fp16)
#pragma unroll
        for (int t = 0; t < 4; t++) {
            const int q = tid * 4 + t;
            const int row = q >> 3, c = q & 7;
            CP16(sbase + row * 144 + c * 16, Qf + (size_t)row * 64 + c * 8);
        }
        CP_COMMIT();

        const int nkb = 4 * qb + 4;
        issueKV(0, 0);
        CP_WAIT(1);  // Q + KV stage 0 ready
        __syncthreads();

        float oacc[8][4];
#pragma unroll
        for (int j = 0; j < 8; j++)
#pragma unroll
            for (int e = 0; e < 4; e++) oacc[j][e] = 0.f;
        float mrow[2] = {-1e30f, -1e30f};
        float lrow[2] = {0.f, 0.f};
        const int qi0 = qb * 256 + w * 16 + (lane >> 2);

        for (int kb = 0; kb < nkb; kb++) {
            const int k0 = kb * 64;
            if (kb + 1 < nkb) { issueKV(kb + 1, (kb + 1) & 1); CP_WAIT(1); }
            else CP_WAIT(0);
            __syncthreads();
            const uint32_t kvb = sbase + 36864 + (kb & 1) * 18432;

            if (qb * 256 + w * 16 + 15 >= k0) {
                // ---- S = Q K^T (fp16 single)
                float sacc[8][4];
#pragma unroll
                for (int j = 0; j < 8; j++)
#pragma unroll
                    for (int e = 0; e < 4; e++) sacc[j][e] = 0.f;
#pragma unroll
                for (int ks = 0; ks < 4; ks++) {
                    uint32_t qf[4];
                    const uint32_t ra = sbase +
                        ((w * 16 + (lane & 15)) * 72 + ks * 16 + (lane >> 4) * 8) * 2;
                    ldm_x4(qf, ra);
                    uint32_t kf[4][4];
#pragma unroll
                    for (int g = 0; g < 4; g++) {
                        const uint32_t rb = kvb +
                            ((g * 16 + (lane & 15)) * 72 + ks * 16 + (lane >> 4) * 8) * 2;
                        ldm_x4(kf[g], rb);
                    }
#pragma unroll
                    for (int nf = 0; nf < 8; nf++) {
                        const int g = nf >> 1, o = nf & 1;
                        uint32_t bf[2] = {kf[g][o], kf[g][o + 2]};
                        mma16816h(sacc[nf], qf, bf);
                    }
                }
                // ---- online softmax
                float mx[2] = {-1e30f, -1e30f};
#pragma unroll
                for (int nf = 0; nf < 8; nf++)
#pragma unroll
                    for (int e = 0; e < 4; e++) {
                        const int col = k0 + nf * 8 + (lane & 3) * 2 + (e & 1);
                        const int r = e >> 1;
                        if (col > qi0 + r * 8) sacc[nf][e] = -1e30f;
                        else mx[r] = fmaxf(mx[r], sacc[nf][e]);
                    }
#pragma unroll
                for (int r = 0; r < 2; r++) {
                    mx[r] = fmaxf(mx[r], __shfl_xor_sync(0xffffffffu, mx[r], 1));
                    mx[r] = fmaxf(mx[r], __shfl_xor_sync(0xffffffffu, mx[r], 2));
                }
                float mn[2], corr[2], sum[2] = {0.f, 0.f};
#pragma unroll
                for (int r = 0; r < 2; r++) {
                    mn[r] = fmaxf(mrow[r], mx[r]);
                    corr[r] = __expf(mrow[r] - mn[r]);
                    mrow[r] = mn[r];
                }
#pragma unroll
                for (int nf = 0; nf < 8; nf++)
#pragma unroll
                    for (int e = 0; e < 4; e++) {
                        const int r = e >> 1;
                        const float pv = __expf(sacc[nf][e] - mn[r]);
                        sacc[nf][e] = pv;
                        sum[r] += pv;
                    }
#pragma unroll
                for (int r = 0; r < 2; r++) {
                    sum[r] += __shfl_xor_sync(0xffffffffu, sum[r], 1);
                    sum[r] += __shfl_xor_sync(0xffffffffu, sum[r], 2);
                    lrow[r] = lrow[r] * corr[r] + sum[r];
                }
#pragma unroll
                for (int nf = 0; nf < 8; nf++)
#pragma unroll
                    for (int e = 0; e < 4; e++) oacc[nf][e] *= corr[e >> 1];
                // ---- PV (fp16 single)
#pragma unroll
                for (int ks = 0; ks < 4; ks++) {
                    uint32_t pf[4];
                    pf[0] = pack_f16(sacc[2 * ks][0], sacc[2 * ks][1]);
                    pf[1] = pack_f16(sacc[2 * ks][2], sacc[2 * ks][3]);
                    pf[2] = pack_f16(sacc[2 * ks + 1][0], sacc[2 * ks + 1][1]);
                    pf[3] = pack_f16(sacc[2 * ks + 1][2], sacc[2 * ks + 1][3]);
                    uint32_t vf[4][4];
#pragma unroll
                    for (int g = 0; g < 4; g++) {
                        const uint32_t rb = kvb + 9216 +
                            ((ks * 16 + (lane & 15)) * 72 + g * 16 + (lane >> 4) * 8) * 2;
                        ldm_x4_t(vf[g], rb);
                    }
#pragma unroll
                    for (int nf = 0; nf < 8; nf++) {
                        const int g = nf >> 1, o = (nf & 1) * 2;
                        uint32_t bf[2] = {vf[g][o], vf[g][o + 1]};
                        mma16816h(oacc[nf], pf, bf);
                    }
                }
            }
            __syncthreads();
        }

        // write out as bf16 hi/lo (input of out-proj GEMM)
        const int bb = bh >> 3, h = bh & 7;
#pragma unroll
        for (int r = 0; r < 2; r++) {
            const float inv = 1.f / lrow[r];
            const int qi = qi0 + r * 8;
            const size_t rowoff = ((size_t)bb * SEQ + qi) * DMODEL + h * HDIM;
#pragma unroll
            for (int nf = 0; nf < 8; nf++) {
                const int hd = nf * 8 + (lane & 3) * 2;
                const float v0 = oacc[nf][r * 2] * inv;
                const float v1 = oacc[nf][r * 2 + 1] * inv;
                const uint32_t hv = pack_hi(v0, v1);
                *reinterpret_cast<uint32_t*>(g_aoh + rowoff + hd) = hv;
                *reinterpret_cast<uint32_t*>(g_aol + rowoff + hd) = pack_lo(v0, v1, hv);
            }
        }
    }
}

// ---------------------------------------------------------------- launch
extern "C" void kernel_launch(void* const* d_in, const int* in_sizes, int n_in,
                              void* d_out, int out_size) {
    const float* x     = (const float*)d_in[0];
    const float* w_qkv = (const float*)d_in[1];
    const float* b_qkv = (const float*)d_in[2];
    const float* w_out = (const float*)d_in[3];
    const float* b_out = (const float*)d_in[4];
    float* out = (float*)d_out;

    bf16 *xh, *xl, *wqh, *wql, *woh, *wol, *aoh, *aol;
    cudaGetSymbolAddress((void**)&xh, g_xh);   cudaGetSymbolAddress((void**)&xl, g_xl);
    cudaGetSymbolAddress((void**)&wqh, g_wqh); cudaGetSymbolAddress((void**)&wql, g_wql);
    cudaGetSymbolAddress((void**)&woh, g_woh); cudaGetSymbolAddress((void**)&wol, g_wol);
    cudaGetSymbolAddress((void**)&aoh, g_aoh); cudaGetSymbolAddress((void**)&aol, g_aol);

    const int SMEM_GEMM = 3 * GSTG;      // 89088
    const int SMEM_ATT  = 73728;
    cudaFuncSetAttribute(gemm_mma<0>, cudaFuncAttributeMaxDynamicSharedMemorySize, SMEM_GEMM);
    cudaFuncSetAttribute(gemm_mma<1>, cudaFuncAttributeMaxDynamicSharedMemorySize, SMEM_GEMM);
    cudaFuncSetAttribute(attn_mma,    cudaFuncAttributeMaxDynamicSharedMemorySize, SMEM_ATT);

    convert_k<<<(MROWS * DMODEL / 4 + 255) / 256, 256>>>(
        (const float4*)x, (uint2*)xh, (uint2*)xl, MROWS * DMODEL / 4);
    convert_k<<<(DMODEL * QKV_N / 4 + 255) / 256, 256>>>(
        (const float4*)w_qkv, (uint2*)wqh, (uint2*)wql, DMODEL * QKV_N / 4);
    convert_k<<<(DMODEL * DMODEL / 4 + 255) / 256, 256>>>(
        (const float4*)w_out, (uint2*)woh, (uint2*)wol, DMODEL * DMODEL / 4);

    // 1) QKV projection -> q/k/v fp16 (Q pre-scaled)
    gemm_mma<0><<<dim3(QKV_N / 64, MROWS / 128), 256, SMEM_GEMM>>>(
        xh, xl, wqh, wql, b_qkv, nullptr, QKV_N);
    // 2) causal attention (fp16 single-pass, balanced wave) -> g_aoh/g_aol
    attn_mma<<<dim3(4, BATCH * NHEAD), 512, SMEM_ATT>>>();
    // 3) output projection -> fp32 out
    gemm_mma<1><<<dim3(DMODEL / 64, MROWS / 128), 256, SMEM_GEMM>>>(
        aoh, aol, woh, wol, b_out, out, DMODEL);
}

// round 10
// speedup vs baseline: 2.5823x; 1.5168x over previous
#include <cuda_runtime.h>
#include <cuda_fp16.h>
#include <cstdint>

// ---------------------------------------------------------------- constants
#define BATCH 4
#define SEQ   2048
#define DMODEL 512
#define NHEAD 8
#define HDIM  64
#define MROWS 8192
#define QKV_N 1536

// ---------------------------------------------------------------- scratch (fp16)
__device__ __half g_xf[(size_t)MROWS * DMODEL];
__device__ __half g_wqf[(size_t)DMODEL * QKV_N];
__device__ __half g_wof[(size_t)DMODEL * DMODEL];
__device__ __half g_qf[(size_t)BATCH * NHEAD * SEQ * HDIM];
__device__ __half g_kf[(size_t)BATCH * NHEAD * SEQ * HDIM];
__device__ __half g_vf[(size_t)BATCH * NHEAD * SEQ * HDIM];
__device__ __half g_aof[(size_t)MROWS * DMODEL];

// ---------------------------------------------------------------- helpers
__device__ __forceinline__ uint32_t smem_u32(const void* p) {
    uint32_t a;
    asm("{ .reg .u64 t; cvta.to.shared.u64 t, %1; cvt.u32.u64 %0, t; }"
        : "=r"(a) : "l"(p));
    return a;
}
__device__ __forceinline__ void ldm_x4(uint32_t* r, uint32_t addr) {
    asm volatile("ldmatrix.sync.aligned.m8n8.x4.shared.b16 {%0,%1,%2,%3}, [%4];"
                 : "=r"(r[0]), "=r"(r[1]), "=r"(r[2]), "=r"(r[3]) : "r"(addr));
}
__device__ __forceinline__ void ldm_x4_t(uint32_t* r, uint32_t addr) {
    asm volatile("ldmatrix.sync.aligned.m8n8.x4.trans.shared.b16 {%0,%1,%2,%3}, [%4];"
                 : "=r"(r[0]), "=r"(r[1]), "=r"(r[2]), "=r"(r[3]) : "r"(addr));
}
__device__ __forceinline__ void mma16816h(float* d, const uint32_t* a, const uint32_t* b) {
    asm volatile(
        "mma.sync.aligned.m16n8k16.row.col.f32.f16.f16.f32 "
        "{%0,%1,%2,%3}, {%4,%5,%6,%7}, {%8,%9}, {%0,%1,%2,%3};"
        : "+f"(d[0]), "+f"(d[1]), "+f"(d[2]), "+f"(d[3])
        : "r"(a[0]), "r"(a[1]), "r"(a[2]), "r"(a[3]), "r"(b[0]), "r"(b[1]));
}
__device__ __forceinline__ uint32_t pack_f16(float a, float b) {
    __half2 h = __floats2half2_rn(a, b);
    return *reinterpret_cast<uint32_t*>(&h);
}

#define CP16(dst, src) \
    asm volatile("cp.async.cg.shared.global [%0], [%1], 16;" :: "r"(dst), "l"(src))
#define CP_COMMIT() asm volatile("cp.async.commit_group;" ::: "memory")
#define CP_WAIT(n)  asm volatile("cp.async.wait_group %0;" :: "n"(n) : "memory")

// ---------------------------------------------------------------- convert fp32 -> fp16
__global__ __launch_bounds__(256)
void convert_f16(const float4* __restrict__ src, uint2* __restrict__ dst, int n4) {
    const int i = blockIdx.x * 256 + threadIdx.x;
    if (i < n4) {
        float4 v = src[i];
        uint2 o;
        o.x = pack_f16(v.x, v.y);
        o.y = pack_f16(v.z, v.w);
        dst[i] = o;
    }
}

// ---------------------------------------------------------------- GEMM (fp16 HMMA)
// C[M,N] = A[M,512] @ W[512,N] (+bias). BM=128 BN=64 BK=32, 8 warps (4m x 2n),
// warp tile 32x32, single fp16 MMA per fragment. 3-stage cp.async, 2 CTAs/SM.
// Stage (14848 B): A[128x40h]@0, B[32x72h]@10240.
#define GSTG 14848
template <int MODE>
__global__ __launch_bounds__(256, 2)
void gemm_f16(const __half* __restrict__ A, const __half* __restrict__ B,
              const float* __restrict__ bias, float* __restrict__ C, int N) {
    extern __shared__ char sm[];
    const uint32_t sbase = smem_u32(sm);
    const int tid = threadIdx.x, lane = tid & 31, w = tid >> 5;
    const int wm = w >> 1, wn = w & 1;
    const int m0 = blockIdx.y * 128, n0 = blockIdx.x * 64;

    float acc[2][4][4];
#pragma unroll
    for (int i = 0; i < 2; i++)
#pragma unroll
        for (int j = 0; j < 4; j++)
#pragma unroll
            for (int e = 0; e < 4; e++) acc[i][j][e] = 0.f;

    // per-thread cp.async chunks: A 2 chunks (of 512), B 1 chunk (of 256)
    const int aq0 = tid * 2;
    const int ar0 = aq0 >> 2, ac0 = aq0 & 3;
    const int ar1 = (aq0 + 1) >> 2, ac1 = (aq0 + 1) & 3;
    const int br = tid >> 3, bc = tid & 7;

    auto issue = [&](int kt) {
        const uint32_t base = sbase + (kt % 3) * GSTG;
        CP16(base + ar0 * 80 + ac0 * 16, A + (size_t)(m0 + ar0) * 512 + kt * 32 + ac0 * 8);
        CP16(base + ar1 * 80 + ac1 * 16, A + (size_t)(m0 + ar1) * 512 + kt * 32 + ac1 * 8);
        CP16(base + 10240 + br * 144 + bc * 16, B + (size_t)(kt * 32 + br) * N + n0 + bc * 8);
        CP_COMMIT();
    };

    issue(0);
    issue(1);
    for (int kt = 0; kt < 16; kt++) {
        CP_WAIT(1);
        __syncthreads();
        if (kt + 2 < 16) issue(kt + 2);
        const uint32_t bA = sbase + (kt % 3) * GSTG;
#pragma unroll
        for (int ks = 0; ks < 2; ks++) {
            uint32_t ah[2][4];
#pragma unroll
            for (int mf = 0; mf < 2; mf++) {
                const uint32_t ra = bA +
                    ((wm * 32 + mf * 16 + (lane & 15)) * 40 + ks * 16 + (lane >> 4) * 8) * 2;
                ldm_x4(ah[mf], ra);
            }
            uint32_t bh[2][4];
#pragma unroll
            for (int g = 0; g < 2; g++) {
                const uint32_t rb = bA + 10240 +
                    ((ks * 16 + (lane & 15)) * 72 + wn * 32 + g * 16 + (lane >> 4) * 8) * 2;
                ldm_x4_t(bh[g], rb);
            }
#pragma unroll
            for (int mf = 0; mf < 2; mf++)
#pragma unroll
                for (int nf = 0; nf < 4; nf++) {
                    const int g = nf >> 1, o = (nf & 1) * 2;
                    uint32_t bf[2] = {bh[g][o], bh[g][o + 1]};
                    mma16816h(acc[mf][nf], ah[mf], bf);
                }
        }
    }

    // epilogue
#pragma unroll
    for (int mf = 0; mf < 2; mf++)
#pragma unroll
        for (int nf = 0; nf < 4; nf++) {
            const int col = n0 + wn * 32 + nf * 8 + (lane & 3) * 2;
            const float b0 = bias[col], b1 = bias[col + 1];
#pragma unroll
            for (int rr = 0; rr < 2; rr++) {
                const int row = m0 + wm * 32 + mf * 16 + (lane >> 2) + rr * 8;
                float v0 = acc[mf][nf][rr * 2] + b0;
                float v1 = acc[mf][nf][rr * 2 + 1] + b1;
                if (MODE == 0) {
                    const int part = col >> 9, ww = col & 511;
                    const int h = ww >> 6, hd = ww & 63;
                    const int bb = row >> 11, sidx = row & 2047;
                    if (part == 0) { v0 *= 0.125f; v1 *= 0.125f; }
                    __half* df = (part == 0) ? g_qf : (part == 1) ? g_kf : g_vf;
                    const size_t idx =
                        ((((size_t)bb * NHEAD + h) * SEQ) + sidx) * HDIM + hd;
                    *reinterpret_cast<uint32_t*>(df + idx) = pack_f16(v0, v1);
                } else {
                    *reinterpret_cast<float2*>(C + (size_t)row * N + col) =
                        make_float2(v0, v1);
                }
            }
        }
}

// ---------------------------------------------------------------- attention (fp16 HMMA)
// 512 threads (16 warps), q-block = 256 rows, grid (4, 32): CTA p handles
// q-blocks {p, 7-p} -> exactly 36 k-block iterations per CTA, one wave.
// Smem: Q@0 (256x72h, 36864 B); KV stage s @ 36864+s*18432: K@+0, V@+9216.
__global__ __launch_bounds__(512)
void attn_mma() {
    extern __shared__ char sm[];
    const uint32_t sbase = smem_u32(sm);
    const int tid = threadIdx.x, lane = tid & 31, w = tid >> 5;
    const int p = blockIdx.x, bh = blockIdx.y;

    const size_t hbase = (size_t)bh * SEQ * HDIM;
    const int qlist[2] = {p, 7 - p};

    auto issueKV = [&](int kb, int buf) {
        const uint32_t base = sbase + 36864 + buf * 18432;
        const int k0 = kb * 64;
        const int row = tid >> 3, c = tid & 7;
        CP16(base + row * 144 + c * 16, g_kf + hbase + (size_t)(k0 + row) * 64 + c * 8);
        CP16(base + 9216 + row * 144 + c * 16, g_vf + hbase + (size_t)(k0 + row) * 64 + c * 8);
        CP_COMMIT();
    };

    for (int qq = 0; qq < 2; qq++) {
        const int qb = qlist[qq];
        const __half* Qf = g_qf + hbase + (size_t)qb * 256 * HDIM;

#pragma unroll
        for (int t = 0; t < 4; t++) {
            const int q = tid * 4 + t;
            const int row = q >> 3, c = q & 7;
            CP16(sbase + row * 144 + c * 16, Qf + (size_t)row * 64 + c * 8);
        }
        CP_COMMIT();

        const int nkb = 4 * qb + 4;
        issueKV(0, 0);
        CP_WAIT(1);
        __syncthreads();

        float oacc[8][4];
#pragma unroll
        for (int j = 0; j < 8; j++)
#pragma unroll
            for (int e = 0; e < 4; e++) oacc[j][e] = 0.f;
        float mrow[2] = {-1e30f, -1e30f};
        float lrow[2] = {0.f, 0.f};
        const int qi0 = qb * 256 + w * 16 + (lane >> 2);

        for (int kb = 0; kb < nkb; kb++) {
            const int k0 = kb * 64;
            if (kb + 1 < nkb) { issueKV(kb + 1, (kb + 1) & 1); CP_WAIT(1); }
            else CP_WAIT(0);
            __syncthreads();
            const uint32_t kvb = sbase + 36864 + (kb & 1) * 18432;

            if (qb * 256 + w * 16 + 15 >= k0) {
                // ---- S = Q K^T
                float sacc[8][4];
#pragma unroll
                for (int j = 0; j < 8; j++)
#pragma unroll
                    for (int e = 0; e < 4; e++) sacc[j][e] = 0.f;
#pragma unroll
                for (int ks = 0; ks < 4; ks++) {
                    uint32_t qf[4];
                    const uint32_t ra = sbase +
                        ((w * 16 + (lane & 15)) * 72 + ks * 16 + (lane >> 4) * 8) * 2;
                    ldm_x4(qf, ra);
                    uint32_t kf[4][4];
#pragma unroll
                    for (int g = 0; g < 4; g++) {
                        const uint32_t rb = kvb +
                            ((g * 16 + (lane & 15)) * 72 + ks * 16 + (lane >> 4) * 8) * 2;
                        ldm_x4(kf[g], rb);
                    }
#pragma unroll
                    for (int nf = 0; nf < 8; nf++) {
                        const int g = nf >> 1, o = nf & 1;
                        uint32_t bf[2] = {kf[g][o], kf[g][o + 2]};
                        mma16816h(sacc[nf], qf, bf);
                    }
                }
                // ---- online softmax
                float mx[2] = {-1e30f, -1e30f};
#pragma unroll
                for (int nf = 0; nf < 8; nf++)
#pragma unroll
                    for (int e = 0; e < 4; e++) {
                        const int col = k0 + nf * 8 + (lane & 3) * 2 + (e & 1);
                        const int r = e >> 1;
                        if (col > qi0 + r * 8) sacc[nf][e] = -1e30f;
                        else mx[r] = fmaxf(mx[r], sacc[nf][e]);
                    }
#pragma unroll
                for (int r = 0; r < 2; r++) {
                    mx[r] = fmaxf(mx[r], __shfl_xor_sync(0xffffffffu, mx[r], 1));
                    mx[r] = fmaxf(mx[r], __shfl_xor_sync(0xffffffffu, mx[r], 2));
                }
                float mn[2], corr[2], sum[2] = {0.f, 0.f};
#pragma unroll
                for (int r = 0; r < 2; r++) {
                    mn[r] = fmaxf(mrow[r], mx[r]);
                    corr[r] = __expf(mrow[r] - mn[r]);
                    mrow[r] = mn[r];
                }
#pragma unroll
                for (int nf = 0; nf < 8; nf++)
#pragma unroll
                    for (int e = 0; e < 4; e++) {
                        const int r = e >> 1;
                        const float pv = __expf(sacc[nf][e] - mn[r]);
                        sacc[nf][e] = pv;
                        sum[r] += pv;
                    }
#pragma unroll
                for (int r = 0; r < 2; r++) {
                    sum[r] += __shfl_xor_sync(0xffffffffu, sum[r], 1);
                    sum[r] += __shfl_xor_sync(0xffffffffu, sum[r], 2);
                    lrow[r] = lrow[r] * corr[r] + sum[r];
                }
#pragma unroll
                for (int nf = 0; nf < 8; nf++)
#pragma unroll
                    for (int e = 0; e < 4; e++) oacc[nf][e] *= corr[e >> 1];
                // ---- PV
#pragma unroll
                for (int ks = 0; ks < 4; ks++) {
                    uint32_t pf[4];
                    pf[0] = pack_f16(sacc[2 * ks][0], sacc[2 * ks][1]);
                    pf[1] = pack_f16(sacc[2 * ks][2], sacc[2 * ks][3]);
                    pf[2] = pack_f16(sacc[2 * ks + 1][0], sacc[2 * ks + 1][1]);
                    pf[3] = pack_f16(sacc[2 * ks + 1][2], sacc[2 * ks + 1][3]);
                    uint32_t vf[4][4];
#pragma unroll
                    for (int g = 0; g < 4; g++) {
                        const uint32_t rb = kvb + 9216 +
                            ((ks * 16 + (lane & 15)) * 72 + g * 16 + (lane >> 4) * 8) * 2;
                        ldm_x4_t(vf[g], rb);
                    }
#pragma unroll
                    for (int nf = 0; nf < 8; nf++) {
                        const int g = nf >> 1, o = (nf & 1) * 2;
                        uint32_t bf[2] = {vf[g][o], vf[g][o + 1]};
                        mma16816h(oacc[nf], pf, bf);
                    }
                }
            }
            __syncthreads();
        }

        // write ao as fp16 (input of out-proj GEMM)
        const int bb = bh >> 3, h = bh & 7;
#pragma unroll
        for (int r = 0; r < 2; r++) {
            const float inv = 1.f / lrow[r];
            const int qi = qi0 + r * 8;
            const size_t rowoff = ((size_t)bb * SEQ + qi) * DMODEL + h * HDIM;
#pragma unroll
            for (int nf = 0; nf < 8; nf++) {
                const int hd = nf * 8 + (lane & 3) * 2;
                *reinterpret_cast<uint32_t*>(g_aof + rowoff + hd) =
                    pack_f16(oacc[nf][r * 2] * inv, oacc[nf][r * 2 + 1] * inv);
            }
        }
    }
}

// ---------------------------------------------------------------- launch
extern "C" void kernel_launch(void* const* d_in, const int* in_sizes, int n_in,
                              void* d_out, int out_size) {
    const float* x     = (const float*)d_in[0];
    const float* w_qkv = (const float*)d_in[1];
    const float* b_qkv = (const float*)d_in[2];
    const float* w_out = (const float*)d_in[3];
    const float* b_out = (const float*)d_in[4];
    float* out = (float*)d_out;

    __half *xf, *wqf, *wof, *aof;
    cudaGetSymbolAddress((void**)&xf, g_xf);
    cudaGetSymbolAddress((void**)&wqf, g_wqf);
    cudaGetSymbolAddress((void**)&wof, g_wof);
    cudaGetSymbolAddress((void**)&aof, g_aof);

    const int SMEM_GEMM = 3 * GSTG;      // 44544
    const int SMEM_ATT  = 73728;
    cudaFuncSetAttribute(gemm_f16<0>, cudaFuncAttributeMaxDynamicSharedMemorySize, SMEM_GEMM);
    cudaFuncSetAttribute(gemm_f16<1>, cudaFuncAttributeMaxDynamicSharedMemorySize, SMEM_GEMM);
    cudaFuncSetAttribute(attn_mma,    cudaFuncAttributeMaxDynamicSharedMemorySize, SMEM_ATT);

    convert_f16<<<(MROWS * DMODEL / 4 + 255) / 256, 256>>>(
        (const float4*)x, (uint2*)xf, MROWS * DMODEL / 4);
    convert_f16<<<(DMODEL * QKV_N / 4 + 255) / 256, 256>>>(
        (const float4*)w_qkv, (uint2*)wqf, DMODEL * QKV_N / 4);
    convert_f16<<<(DMODEL * DMODEL / 4 + 255) / 256, 256>>>(
        (const float4*)w_out, (uint2*)wof, DMODEL * DMODEL / 4);

    // 1) QKV projection -> q/k/v fp16 (Q pre-scaled)
    gemm_f16<0><<<dim3(QKV_N / 64, MROWS / 128), 256, SMEM_GEMM>>>(
        xf, wqf, b_qkv, nullptr, QKV_N);
    // 2) causal attention (fp16, balanced wave) -> g_aof
    attn_mma<<<dim3(4, BATCH * NHEAD), 512, SMEM_ATT>>>();
    // 3) output projection -> fp32 out
    gemm_f16<1><<<dim3(DMODEL / 64, MROWS / 128), 256, SMEM_GEMM>>>(
        aof, wof, b_out, out, DMODEL);
}

// round 11
// speedup vs baseline: 2.7820x; 1.0773x over previous
#include <cuda_runtime.h>
#include <cuda_fp16.h>
#include <cstdint>

// ---------------------------------------------------------------- constants
#define BATCH 4
#define SEQ   2048
#define DMODEL 512
#define NHEAD 8
#define HDIM  64
#define MROWS 8192
#define QKV_N 1536

// ---------------------------------------------------------------- scratch (fp16)
__device__ __half g_xf[(size_t)MROWS * DMODEL];
__device__ __half g_wqf[(size_t)DMODEL * QKV_N];
__device__ __half g_wof[(size_t)DMODEL * DMODEL];
__device__ __half g_qf[(size_t)BATCH * NHEAD * SEQ * HDIM];
__device__ __half g_kf[(size_t)BATCH * NHEAD * SEQ * HDIM];
__device__ __half g_vf[(size_t)BATCH * NHEAD * SEQ * HDIM];
__device__ __half g_aof[(size_t)MROWS * DMODEL];

// ---------------------------------------------------------------- helpers
__device__ __forceinline__ uint32_t smem_u32(const void* p) {
    uint32_t a;
    asm("{ .reg .u64 t; cvta.to.shared.u64 t, %1; cvt.u32.u64 %0, t; }"
        : "=r"(a) : "l"(p));
    return a;
}
__device__ __forceinline__ void ldm_x4(uint32_t* r, uint32_t addr) {
    asm volatile("ldmatrix.sync.aligned.m8n8.x4.shared.b16 {%0,%1,%2,%3}, [%4];"
                 : "=r"(r[0]), "=r"(r[1]), "=r"(r[2]), "=r"(r[3]) : "r"(addr));
}
__device__ __forceinline__ void ldm_x4_t(uint32_t* r, uint32_t addr) {
    asm volatile("ldmatrix.sync.aligned.m8n8.x4.trans.shared.b16 {%0,%1,%2,%3}, [%4];"
                 : "=r"(r[0]), "=r"(r[1]), "=r"(r[2]), "=r"(r[3]) : "r"(addr));
}
__device__ __forceinline__ void mma16816h(float* d, const uint32_t* a, const uint32_t* b) {
    asm volatile(
        "mma.sync.aligned.m16n8k16.row.col.f32.f16.f16.f32 "
        "{%0,%1,%2,%3}, {%4,%5,%6,%7}, {%8,%9}, {%0,%1,%2,%3};"
        : "+f"(d[0]), "+f"(d[1]), "+f"(d[2]), "+f"(d[3])
        : "r"(a[0]), "r"(a[1]), "r"(a[2]), "r"(a[3]), "r"(b[0]), "r"(b[1]));
}
__device__ __forceinline__ uint32_t pack_f16(float a, float b) {
    __half2 h = __floats2half2_rn(a, b);
    return *reinterpret_cast<uint32_t*>(&h);
}

#define CP16(dst, src) \
    asm volatile("cp.async.cg.shared.global [%0], [%1], 16;" :: "r"(dst), "l"(src))
#define CP_COMMIT() asm volatile("cp.async.commit_group;" ::: "memory")
#define CP_WAIT(n)  asm volatile("cp.async.wait_group %0;" :: "n"(n) : "memory")

// ---------------------------------------------------------------- fused convert fp32 -> fp16
#define N4_X  (MROWS * DMODEL / 4)                   // 1048576
#define N4_WQ (DMODEL * QKV_N / 4)                   // 196608
#define N4_WO (DMODEL * DMODEL / 4)                  // 65536
#define N4_TOT (N4_X + N4_WQ + N4_WO)                // 1310720
__global__ __launch_bounds__(256)
void convert_all(const float4* __restrict__ x, const float4* __restrict__ wq,
                 const float4* __restrict__ wo) {
    const int i = blockIdx.x * 256 + threadIdx.x;
    if (i >= N4_TOT) return;
    const float4* src;
    uint2* dst;
    int j = i;
    if (j < N4_X) { src = x; dst = (uint2*)g_xf; }
    else if ((j -= N4_X) < N4_WQ) { src = wq; dst = (uint2*)g_wqf; }
    else { j -= N4_WQ; src = wo; dst = (uint2*)g_wof; }
    float4 v = src[j];
    uint2 o;
    o.x = pack_f16(v.x, v.y);
    o.y = pack_f16(v.z, v.w);
    dst[j] = o;
}

// ---------------------------------------------------------------- GEMM (fp16 HMMA)
// C[M,N] = A[M,512] @ W[512,N] (+bias). BM=128 BN=128 BK=32, 8 warps (4m x 2n),
// warp tile 32x64, single fp16 MMA. 3-stage cp.async, 2 CTAs/SM.
// Stage (18944 B): A[128x40h]@0, B[32x136h]@10240.
#define GSTG 18944
template <int MODE>
__global__ __launch_bounds__(256, 2)
void gemm_f16(const __half* __restrict__ A, const __half* __restrict__ B,
              const float* __restrict__ bias, float* __restrict__ C, int N) {
    extern __shared__ char sm[];
    const uint32_t sbase = smem_u32(sm);
    const int tid = threadIdx.x, lane = tid & 31, w = tid >> 5;
    const int wm = w >> 1, wn = w & 1;
    const int m0 = blockIdx.y * 128, n0 = blockIdx.x * 128;

    float acc[2][8][4];
#pragma unroll
    for (int i = 0; i < 2; i++)
#pragma unroll
        for (int j = 0; j < 8; j++)
#pragma unroll
            for (int e = 0; e < 4; e++) acc[i][j][e] = 0.f;

    // per-thread cp.async chunks: A 2 of 512, B 2 of 512
    const int q0 = tid * 2;
    const int ar0 = q0 >> 2, ac0 = q0 & 3;
    const int ar1 = (q0 + 1) >> 2, ac1 = (q0 + 1) & 3;
    const int br0 = q0 >> 4, bc0 = q0 & 15;
    const int br1 = (q0 + 1) >> 4, bc1 = (q0 + 1) & 15;

    auto issue = [&](int kt) {
        const uint32_t base = sbase + (kt % 3) * GSTG;
        CP16(base + ar0 * 80 + ac0 * 16, A + (size_t)(m0 + ar0) * 512 + kt * 32 + ac0 * 8);
        CP16(base + ar1 * 80 + ac1 * 16, A + (size_t)(m0 + ar1) * 512 + kt * 32 + ac1 * 8);
        CP16(base + 10240 + br0 * 272 + bc0 * 16, B + (size_t)(kt * 32 + br0) * N + n0 + bc0 * 8);
        CP16(base + 10240 + br1 * 272 + bc1 * 16, B + (size_t)(kt * 32 + br1) * N + n0 + bc1 * 8);
        CP_COMMIT();
    };

    issue(0);
    issue(1);
    for (int kt = 0; kt < 16; kt++) {
        CP_WAIT(1);
        __syncthreads();
        if (kt + 2 < 16) issue(kt + 2);
        const uint32_t bA = sbase + (kt % 3) * GSTG;
#pragma unroll
        for (int ks = 0; ks < 2; ks++) {
            uint32_t ah[2][4];
#pragma unroll
            for (int mf = 0; mf < 2; mf++) {
                const uint32_t ra = bA +
                    ((wm * 32 + mf * 16 + (lane & 15)) * 40 + ks * 16 + (lane >> 4) * 8) * 2;
                ldm_x4(ah[mf], ra);
            }
            uint32_t bh[4][4];
#pragma unroll
            for (int g = 0; g < 4; g++) {
                const uint32_t rb = bA + 10240 +
                    ((ks * 16 + (lane & 15)) * 136 + wn * 64 + g * 16 + (lane >> 4) * 8) * 2;
                ldm_x4_t(bh[g], rb);
            }
#pragma unroll
            for (int mf = 0; mf < 2; mf++)
#pragma unroll
                for (int nf = 0; nf < 8; nf++) {
                    const int g = nf >> 1, o = (nf & 1) * 2;
                    uint32_t bf[2] = {bh[g][o], bh[g][o + 1]};
                    mma16816h(acc[mf][nf], ah[mf], bf);
                }
        }
    }

    // epilogue
#pragma unroll
    for (int mf = 0; mf < 2; mf++)
#pragma unroll
        for (int nf = 0; nf < 8; nf++) {
            const int col = n0 + wn * 64 + nf * 8 + (lane & 3) * 2;
            const float b0 = bias[col], b1 = bias[col + 1];
#pragma unroll
            for (int rr = 0; rr < 2; rr++) {
                const int row = m0 + wm * 32 + mf * 16 + (lane >> 2) + rr * 8;
                float v0 = acc[mf][nf][rr * 2] + b0;
                float v1 = acc[mf][nf][rr * 2 + 1] + b1;
                if (MODE == 0) {
                    const int part = col >> 9, ww = col & 511;
                    const int h = ww >> 6, hd = ww & 63;
                    const int bb = row >> 11, sidx = row & 2047;
                    if (part == 0) { v0 *= 0.125f; v1 *= 0.125f; }
                    __half* df = (part == 0) ? g_qf : (part == 1) ? g_kf : g_vf;
                    const size_t idx =
                        ((((size_t)bb * NHEAD + h) * SEQ) + sidx) * HDIM + hd;
                    *reinterpret_cast<uint32_t*>(df + idx) = pack_f16(v0, v1);
                } else {
                    *reinterpret_cast<float2*>(C + (size_t)row * N + col) =
                        make_float2(v0, v1);
                }
            }
        }
}

// ---------------------------------------------------------------- attention (fp16 HMMA)
// 512 threads (16 warps), q-block = 256 rows, grid (4, 32): CTA p handles
// q-blocks {p, 7-p} -> exactly 36 k-block iterations per CTA, one wave.
// Smem: Q@0 (256x72h, 36864 B); KV stage s @ 36864+s*18432: K@+0, V@+9216.
__global__ __launch_bounds__(512)
void attn_mma() {
    extern __shared__ char sm[];
    const uint32_t sbase = smem_u32(sm);
    const int tid = threadIdx.x, lane = tid & 31, w = tid >> 5;
    const int p = blockIdx.x, bh = blockIdx.y;

    const size_t hbase = (size_t)bh * SEQ * HDIM;
    const int qlist[2] = {p, 7 - p};

    auto issueKV = [&](int kb, int buf) {
        const uint32_t base = sbase + 36864 + buf * 18432;
        const int k0 = kb * 64;
        const int row = tid >> 3, c = tid & 7;
        CP16(base + row * 144 + c * 16, g_kf + hbase + (size_t)(k0 + row) * 64 + c * 8);
        CP16(base + 9216 + row * 144 + c * 16, g_vf + hbase + (size_t)(k0 + row) * 64 + c * 8);
        CP_COMMIT();
    };

    for (int qq = 0; qq < 2; qq++) {
        const int qb = qlist[qq];
        const __half* Qf = g_qf + hbase + (size_t)qb * 256 * HDIM;

#pragma unroll
        for (int t = 0; t < 4; t++) {
            const int q = tid * 4 + t;
            const int row = q >> 3, c = q & 7;
            CP16(sbase + row * 144 + c * 16, Qf + (size_t)row * 64 + c * 8);
        }
        CP_COMMIT();

        const int nkb = 4 * qb + 4;
        issueKV(0, 0);
        CP_WAIT(1);
        __syncthreads();

        float oacc[8][4];
#pragma unroll
        for (int j = 0; j < 8; j++)
#pragma unroll
            for (int e = 0; e < 4; e++) oacc[j][e] = 0.f;
        float mrow[2] = {-1e30f, -1e30f};
        float lrow[2] = {0.f, 0.f};
        const int qi0 = qb * 256 + w * 16 + (lane >> 2);

        for (int kb = 0; kb < nkb; kb++) {
            const int k0 = kb * 64;
            if (kb + 1 < nkb) { issueKV(kb + 1, (kb + 1) & 1); CP_WAIT(1); }
            else CP_WAIT(0);
            __syncthreads();
            const uint32_t kvb = sbase + 36864 + (kb & 1) * 18432;

            if (qb * 256 + w * 16 + 15 >= k0) {
                // ---- S = Q K^T
                float sacc[8][4];
#pragma unroll
                for (int j = 0; j < 8; j++)
#pragma unroll
                    for (int e = 0; e < 4; e++) sacc[j][e] = 0.f;
#pragma unroll
                for (int ks = 0; ks < 4; ks++) {
                    uint32_t qf[4];
                    const uint32_t ra = sbase +
                        ((w * 16 + (lane & 15)) * 72 + ks * 16 + (lane >> 4) * 8) * 2;
                    ldm_x4(qf, ra);
                    uint32_t kf[4][4];
#pragma unroll
                    for (int g = 0; g < 4; g++) {
                        const uint32_t rb = kvb +
                            ((g * 16 + (lane & 15)) * 72 + ks * 16 + (lane >> 4) * 8) * 2;
                        ldm_x4(kf[g], rb);
                    }
#pragma unroll
                    for (int nf = 0; nf < 8; nf++) {
                        const int g = nf >> 1, o = nf & 1;
                        uint32_t bf[2] = {kf[g][o], kf[g][o + 2]};
                        mma16816h(sacc[nf], qf, bf);
                    }
                }
                // ---- online softmax
                float mx[2] = {-1e30f, -1e30f};
#pragma unroll
                for (int nf = 0; nf < 8; nf++)
#pragma unroll
                    for (int e = 0; e < 4; e++) {
                        const int col = k0 + nf * 8 + (lane & 3) * 2 + (e & 1);
                        const int r = e >> 1;
                        if (col > qi0 + r * 8) sacc[nf][e] = -1e30f;
                        else mx[r] = fmaxf(mx[r], sacc[nf][e]);
                    }
#pragma unroll
                for (int r = 0; r < 2; r++) {
                    mx[r] = fmaxf(mx[r], __shfl_xor_sync(0xffffffffu, mx[r], 1));
                    mx[r] = fmaxf(mx[r], __shfl_xor_sync(0xffffffffu, mx[r], 2));
                }
                float mn[2], corr[2], sum[2] = {0.f, 0.f};
#pragma unroll
                for (int r = 0; r < 2; r++) {
                    mn[r] = fmaxf(mrow[r], mx[r]);
                    corr[r] = __expf(mrow[r] - mn[r]);
                    mrow[r] = mn[r];
                }
#pragma unroll
                for (int nf = 0; nf < 8; nf++)
#pragma unroll
                    for (int e = 0; e < 4; e++) {
                        const int r = e >> 1;
                        const float pv = __expf(sacc[nf][e] - mn[r]);
                        sacc[nf][e] = pv;
                        sum[r] += pv;
                    }
#pragma unroll
                for (int r = 0; r < 2; r++) {
                    sum[r] += __shfl_xor_sync(0xffffffffu, sum[r], 1);
                    sum[r] += __shfl_xor_sync(0xffffffffu, sum[r], 2);
                    lrow[r] = lrow[r] * corr[r] + sum[r];
                }
#pragma unroll
                for (int nf = 0; nf < 8; nf++)
#pragma unroll
                    for (int e = 0; e < 4; e++) oacc[nf][e] *= corr[e >> 1];
                // ---- PV
#pragma unroll
                for (int ks = 0; ks < 4; ks++) {
                    uint32_t pf[4];
                    pf[0] = pack_f16(sacc[2 * ks][0], sacc[2 * ks][1]);
                    pf[1] = pack_f16(sacc[2 * ks][2], sacc[2 * ks][3]);
                    pf[2] = pack_f16(sacc[2 * ks + 1][0], sacc[2 * ks + 1][1]);
                    pf[3] = pack_f16(sacc[2 * ks + 1][2], sacc[2 * ks + 1][3]);
                    uint32_t vf[4][4];
#pragma unroll
                    for (int g = 0; g < 4; g++) {
                        const uint32_t rb = kvb + 9216 +
                            ((ks * 16 + (lane & 15)) * 72 + g * 16 + (lane >> 4) * 8) * 2;
                        ldm_x4_t(vf[g], rb);
                    }
#pragma unroll
                    for (int nf = 0; nf < 8; nf++) {
                        const int g = nf >> 1, o = (nf & 1) * 2;
                        uint32_t bf[2] = {vf[g][o], vf[g][o + 1]};
                        mma16816h(oacc[nf], pf, bf);
                    }
                }
            }
            __syncthreads();
        }

        // write ao as fp16 (input of out-proj GEMM)
        const int bb = bh >> 3, h = bh & 7;
#pragma unroll
        for (int r = 0; r < 2; r++) {
            const float inv = 1.f / lrow[r];
            const int qi = qi0 + r * 8;
            const size_t rowoff = ((size_t)bb * SEQ + qi) * DMODEL + h * HDIM;
#pragma unroll
            for (int nf = 0; nf < 8; nf++) {
                const int hd = nf * 8 + (lane & 3) * 2;
                *reinterpret_cast<uint32_t*>(g_aof + rowoff + hd) =
                    pack_f16(oacc[nf][r * 2] * inv, oacc[nf][r * 2 + 1] * inv);
            }
        }
    }
}

// ---------------------------------------------------------------- launch
extern "C" void kernel_launch(void* const* d_in, const int* in_sizes, int n_in,
                              void* d_out, int out_size) {
    const float* x     = (const float*)d_in[0];
    const float* w_qkv = (const float*)d_in[1];
    const float* b_qkv = (const float*)d_in[2];
    const float* w_out = (const float*)d_in[3];
    const float* b_out = (const float*)d_in[4];
    float* out = (float*)d_out;

    __half *xf, *wqf, *wof, *aof;
    cudaGetSymbolAddress((void**)&xf, g_xf);
    cudaGetSymbolAddress((void**)&wqf, g_wqf);
    cudaGetSymbolAddress((void**)&wof, g_wof);
    cudaGetSymbolAddress((void**)&aof, g_aof);

    const int SMEM_GEMM = 3 * GSTG;      // 56832
    const int SMEM_ATT  = 73728;
    cudaFuncSetAttribute(gemm_f16<0>, cudaFuncAttributeMaxDynamicSharedMemorySize, SMEM_GEMM);
    cudaFuncSetAttribute(gemm_f16<1>, cudaFuncAttributeMaxDynamicSharedMemorySize, SMEM_GEMM);
    cudaFuncSetAttribute(attn_mma,    cudaFuncAttributeMaxDynamicSharedMemorySize, SMEM_ATT);

    // fused pre-convert (x, w_qkv, w_out -> fp16)
    convert_all<<<(N4_TOT + 255) / 256, 256>>>(
        (const float4*)x, (const float4*)w_qkv, (const float4*)w_out);

    // 1) QKV projection -> q/k/v fp16 (Q pre-scaled)
    gemm_f16<0><<<dim3(QKV_N / 128, MROWS / 128), 256, SMEM_GEMM>>>(
        xf, wqf, b_qkv, nullptr, QKV_N);
    // 2) causal attention (fp16, balanced wave) -> g_aof
    attn_mma<<<dim3(4, BATCH * NHEAD), 512, SMEM_ATT>>>();
    // 3) output projection -> fp32 out
    gemm_f16<1><<<dim3(DMODEL / 128, MROWS / 128), 256, SMEM_GEMM>>>(
        aof, wof, b_out, out, DMODEL);
}

// round 12
// speedup vs baseline: 3.1414x; 1.1292x over previous
#include <cuda_runtime.h>
#include <cuda_fp16.h>
#include <cstdint>

// ---------------------------------------------------------------- constants
#define BATCH 4
#define SEQ   2048
#define DMODEL 512
#define NHEAD 8
#define HDIM  64
#define MROWS 8192
#define QKV_N 1536

// ---------------------------------------------------------------- scratch (fp16)
__device__ __half g_xf[(size_t)MROWS * DMODEL];
__device__ __half g_wqf[(size_t)DMODEL * QKV_N];
__device__ __half g_wof[(size_t)DMODEL * DMODEL];
__device__ __half g_qf[(size_t)BATCH * NHEAD * SEQ * HDIM];
__device__ __half g_kf[(size_t)BATCH * NHEAD * SEQ * HDIM];
__device__ __half g_vf[(size_t)BATCH * NHEAD * SEQ * HDIM];
__device__ __half g_aof[(size_t)MROWS * DMODEL];

// ---------------------------------------------------------------- helpers
__device__ __forceinline__ uint32_t smem_u32(const void* p) {
    uint32_t a;
    asm("{ .reg .u64 t; cvta.to.shared.u64 t, %1; cvt.u32.u64 %0, t; }"
        : "=r"(a) : "l"(p));
    return a;
}
__device__ __forceinline__ void ldm_x4(uint32_t* r, uint32_t addr) {
    asm volatile("ldmatrix.sync.aligned.m8n8.x4.shared.b16 {%0,%1,%2,%3}, [%4];"
                 : "=r"(r[0]), "=r"(r[1]), "=r"(r[2]), "=r"(r[3]) : "r"(addr));
}
__device__ __forceinline__ void ldm_x4_t(uint32_t* r, uint32_t addr) {
    asm volatile("ldmatrix.sync.aligned.m8n8.x4.trans.shared.b16 {%0,%1,%2,%3}, [%4];"
                 : "=r"(r[0]), "=r"(r[1]), "=r"(r[2]), "=r"(r[3]) : "r"(addr));
}
__device__ __forceinline__ void mma16816h(float* d, const uint32_t* a, const uint32_t* b) {
    asm volatile(
        "mma.sync.aligned.m16n8k16.row.col.f32.f16.f16.f32 "
        "{%0,%1,%2,%3}, {%4,%5,%6,%7}, {%8,%9}, {%0,%1,%2,%3};"
        : "+f"(d[0]), "+f"(d[1]), "+f"(d[2]), "+f"(d[3])
        : "r"(a[0]), "r"(a[1]), "r"(a[2]), "r"(a[3]), "r"(b[0]), "r"(b[1]));
}
__device__ __forceinline__ uint32_t pack_f16(float a, float b) {
    __half2 h = __floats2half2_rn(a, b);
    return *reinterpret_cast<uint32_t*>(&h);
}
__device__ __forceinline__ float ex2f(float x) {
    float r;
    asm("ex2.approx.f32 %0, %1;" : "=f"(r) : "f"(x));
    return r;
}

#define CP16(dst, src) \
    asm volatile("cp.async.cg.shared.global [%0], [%1], 16;" :: "r"(dst), "l"(src))
#define CP_COMMIT() asm volatile("cp.async.commit_group;" ::: "memory")
#define CP_WAIT(n)  asm volatile("cp.async.wait_group %0;" :: "n"(n) : "memory")

// Q scale with log2(e) folded in: scores come out in log2 domain.
#define QSCALE (0.125f * 1.4426950408889634f)

// ---------------------------------------------------------------- fused convert fp32 -> fp16
#define N4_X  (MROWS * DMODEL / 4)
#define N4_WQ (DMODEL * QKV_N / 4)
#define N4_WO (DMODEL * DMODEL / 4)
#define N4_TOT (N4_X + N4_WQ + N4_WO)
__global__ __launch_bounds__(256)
void convert_all(const float4* __restrict__ x, const float4* __restrict__ wq,
                 const float4* __restrict__ wo) {
    const int i = blockIdx.x * 256 + threadIdx.x;
    if (i >= N4_TOT) return;
    const float4* src;
    uint2* dst;
    int j = i;
    if (j < N4_X) { src = x; dst = (uint2*)g_xf; }
    else if ((j -= N4_X) < N4_WQ) { src = wq; dst = (uint2*)g_wqf; }
    else { j -= N4_WQ; src = wo; dst = (uint2*)g_wof; }
    float4 v = src[j];
    uint2 o;
    o.x = pack_f16(v.x, v.y);
    o.y = pack_f16(v.z, v.w);
    dst[j] = o;
}

// ---------------------------------------------------------------- GEMM (fp16 HMMA)
// BM=128 BN=128 BK=32, 8 warps (4m x 2n), warp tile 32x64. 3-stage cp.async.
// Stage (18944 B): A[128x40h]@0, B[32x136h]@10240.
#define GSTG 18944
template <int MODE>
__global__ __launch_bounds__(256, 2)
void gemm_f16(const __half* __restrict__ A, const __half* __restrict__ B,
              const float* __restrict__ bias, float* __restrict__ C, int N) {
    extern __shared__ char sm[];
    const uint32_t sbase = smem_u32(sm);
    const int tid = threadIdx.x, lane = tid & 31, w = tid >> 5;
    const int wm = w >> 1, wn = w & 1;
    const int m0 = blockIdx.y * 128, n0 = blockIdx.x * 128;

    float acc[2][8][4];
#pragma unroll
    for (int i = 0; i < 2; i++)
#pragma unroll
        for (int j = 0; j < 8; j++)
#pragma unroll
            for (int e = 0; e < 4; e++) acc[i][j][e] = 0.f;

    const int q0 = tid * 2;
    const int ar0 = q0 >> 2, ac0 = q0 & 3;
    const int ar1 = (q0 + 1) >> 2, ac1 = (q0 + 1) & 3;
    const int br0 = q0 >> 4, bc0 = q0 & 15;
    const int br1 = (q0 + 1) >> 4, bc1 = (q0 + 1) & 15;

    auto issue = [&](int kt) {
        const uint32_t base = sbase + (kt % 3) * GSTG;
        CP16(base + ar0 * 80 + ac0 * 16, A + (size_t)(m0 + ar0) * 512 + kt * 32 + ac0 * 8);
        CP16(base + ar1 * 80 + ac1 * 16, A + (size_t)(m0 + ar1) * 512 + kt * 32 + ac1 * 8);
        CP16(base + 10240 + br0 * 272 + bc0 * 16, B + (size_t)(kt * 32 + br0) * N + n0 + bc0 * 8);
        CP16(base + 10240 + br1 * 272 + bc1 * 16, B + (size_t)(kt * 32 + br1) * N + n0 + bc1 * 8);
        CP_COMMIT();
    };

    issue(0);
    issue(1);
    for (int kt = 0; kt < 16; kt++) {
        CP_WAIT(1);
        __syncthreads();
        if (kt + 2 < 16) issue(kt + 2);
        const uint32_t bA = sbase + (kt % 3) * GSTG;
#pragma unroll
        for (int ks = 0; ks < 2; ks++) {
            uint32_t ah[2][4];
#pragma unroll
            for (int mf = 0; mf < 2; mf++) {
                const uint32_t ra = bA +
                    ((wm * 32 + mf * 16 + (lane & 15)) * 40 + ks * 16 + (lane >> 4) * 8) * 2;
                ldm_x4(ah[mf], ra);
            }
            uint32_t bh[4][4];
#pragma unroll
            for (int g = 0; g < 4; g++) {
                const uint32_t rb = bA + 10240 +
                    ((ks * 16 + (lane & 15)) * 136 + wn * 64 + g * 16 + (lane >> 4) * 8) * 2;
                ldm_x4_t(bh[g], rb);
            }
#pragma unroll
            for (int mf = 0; mf < 2; mf++)
#pragma unroll
                for (int nf = 0; nf < 8; nf++) {
                    const int g = nf >> 1, o = (nf & 1) * 2;
                    uint32_t bf[2] = {bh[g][o], bh[g][o + 1]};
                    mma16816h(acc[mf][nf], ah[mf], bf);
                }
        }
    }

    // epilogue
#pragma unroll
    for (int mf = 0; mf < 2; mf++)
#pragma unroll
        for (int nf = 0; nf < 8; nf++) {
            const int col = n0 + wn * 64 + nf * 8 + (lane & 3) * 2;
            const float b0 = bias[col], b1 = bias[col + 1];
#pragma unroll
            for (int rr = 0; rr < 2; rr++) {
                const int row = m0 + wm * 32 + mf * 16 + (lane >> 2) + rr * 8;
                float v0 = acc[mf][nf][rr * 2] + b0;
                float v1 = acc[mf][nf][rr * 2 + 1] + b1;
                if (MODE == 0) {
                    const int part = col >> 9, ww = col & 511;
                    const int h = ww >> 6, hd = ww & 63;
                    const int bb = row >> 11, sidx = row & 2047;
                    if (part == 0) { v0 *= QSCALE; v1 *= QSCALE; }
                    __half* df = (part == 0) ? g_qf : (part == 1) ? g_kf : g_vf;
                    const size_t idx =
                        ((((size_t)bb * NHEAD + h) * SEQ) + sidx) * HDIM + hd;
                    *reinterpret_cast<uint32_t*>(df + idx) = pack_f16(v0, v1);
                } else {
                    *reinterpret_cast<float2*>(C + (size_t)row * N + col) =
                        make_float2(v0, v1);
                }
            }
        }
}

// ---------------------------------------------------------------- attention (fp16 HMMA)
// 512 threads (16 warps), q-block = 256, grid (4,32); CTA p -> {p, 7-p} (36 iters).
// Triple-buffered KV ring -> ONE __syncthreads per k-block.
// Scores in log2 domain (QSCALE), softmax via raw ex2.approx.
// Smem: Q@0 (256x72h = 36864 B); KV stage s @ 36864+s*18432 (K@+0, V@+9216).
__global__ __launch_bounds__(512)
void attn_mma() {
    extern __shared__ char sm[];
    const uint32_t sbase = smem_u32(sm);
    const int tid = threadIdx.x, lane = tid & 31, w = tid >> 5;
    const int p = blockIdx.x, bh = blockIdx.y;

    const size_t hbase = (size_t)bh * SEQ * HDIM;
    const int qlist[2] = {p, 7 - p};

    auto issueKV = [&](int kb) {
        const uint32_t base = sbase + 36864 + (kb % 3) * 18432;
        const int k0 = kb * 64;
        const int row = tid >> 3, c = tid & 7;
        CP16(base + row * 144 + c * 16, g_kf + hbase + (size_t)(k0 + row) * 64 + c * 8);
        CP16(base + 9216 + row * 144 + c * 16, g_vf + hbase + (size_t)(k0 + row) * 64 + c * 8);
        CP_COMMIT();
    };

    for (int qq = 0; qq < 2; qq++) {
        const int qb = qlist[qq];
        const __half* Qf = g_qf + hbase + (size_t)qb * 256 * HDIM;

        __syncthreads();   // guard Q smem rewrite vs previous qq readers
#pragma unroll
        for (int t = 0; t < 4; t++) {
            const int q = tid * 4 + t;
            const int row = q >> 3, c = q & 7;
            CP16(sbase + row * 144 + c * 16, Qf + (size_t)row * 64 + c * 8);
        }
        CP_COMMIT();

        const int nkb = 4 * qb + 4;
        issueKV(0);

        float oacc[8][4];
#pragma unroll
        for (int j = 0; j < 8; j++)
#pragma unroll
            for (int e = 0; e < 4; e++) oacc[j][e] = 0.f;
        float mrow[2] = {-1e30f, -1e30f};
        float lrow[2] = {0.f, 0.f};
        const int qi0 = qb * 256 + w * 16 + (lane >> 2);

        for (int kb = 0; kb < nkb; kb++) {
            const int k0 = kb * 64;
            if (kb + 1 < nkb) { issueKV(kb + 1); CP_WAIT(1); }
            else CP_WAIT(0);
            __syncthreads();   // single sync per iteration (3-buffer ring)
            const uint32_t kvb = sbase + 36864 + (kb % 3) * 18432;

            if (qb * 256 + w * 16 + 15 >= k0) {
                // ---- S = Q K^T (log2-domain scores)
                float sacc[8][4];
#pragma unroll
                for (int j = 0; j < 8; j++)
#pragma unroll
                    for (int e = 0; e < 4; e++) sacc[j][e] = 0.f;
#pragma unroll
                for (int ks = 0; ks < 4; ks++) {
                    uint32_t qf[4];
                    const uint32_t ra = sbase +
                        ((w * 16 + (lane & 15)) * 72 + ks * 16 + (lane >> 4) * 8) * 2;
                    ldm_x4(qf, ra);
                    uint32_t kf[4][4];
#pragma unroll
                    for (int g = 0; g < 4; g++) {
                        const uint32_t rb = kvb +
                            ((g * 16 + (lane & 15)) * 72 + ks * 16 + (lane >> 4) * 8) * 2;
                        ldm_x4(kf[g], rb);
                    }
#pragma unroll
                    for (int nf = 0; nf < 8; nf++) {
                        const int g = nf >> 1, o = nf & 1;
                        uint32_t bf[2] = {kf[g][o], kf[g][o + 2]};
                        mma16816h(sacc[nf], qf, bf);
                    }
                }
                // ---- online softmax (ex2-domain)
                float mx[2] = {-1e30f, -1e30f};
                if (k0 + 63 <= qi0) {
                    // fully visible block: no masking needed
#pragma unroll
                    for (int nf = 0; nf < 8; nf++)
#pragma unroll
                        for (int e = 0; e < 4; e++)
                            mx[e >> 1] = fmaxf(mx[e >> 1], sacc[nf][e]);
                } else {
#pragma unroll
                    for (int nf = 0; nf < 8; nf++)
#pragma unroll
                        for (int e = 0; e < 4; e++) {
                            const int col = k0 + nf * 8 + (lane & 3) * 2 + (e & 1);
                            const int r = e >> 1;
                            if (col > qi0 + r * 8) sacc[nf][e] = -1e30f;
                            else mx[r] = fmaxf(mx[r], sacc[nf][e]);
                        }
                }
#pragma unroll
                for (int r = 0; r < 2; r++) {
                    mx[r] = fmaxf(mx[r], __shfl_xor_sync(0xffffffffu, mx[r], 1));
                    mx[r] = fmaxf(mx[r], __shfl_xor_sync(0xffffffffu, mx[r], 2));
                }
                float mn[2], corr[2], sum[2] = {0.f, 0.f};
#pragma unroll
                for (int r = 0; r < 2; r++) {
                    mn[r] = fmaxf(mrow[r], mx[r]);
                    corr[r] = ex2f(mrow[r] - mn[r]);
                    mrow[r] = mn[r];
                }
#pragma unroll
                for (int nf = 0; nf < 8; nf++)
#pragma unroll
                    for (int e = 0; e < 4; e++) {
                        const int r = e >> 1;
                        const float pv = ex2f(sacc[nf][e] - mn[r]);
                        sacc[nf][e] = pv;
                        sum[r] += pv;
                    }
#pragma unroll
                for (int r = 0; r < 2; r++) {
                    sum[r] += __shfl_xor_sync(0xffffffffu, sum[r], 1);
                    sum[r] += __shfl_xor_sync(0xffffffffu, sum[r], 2);
                    lrow[r] = lrow[r] * corr[r] + sum[r];
                }
#pragma unroll
                for (int nf = 0; nf < 8; nf++)
#pragma unroll
                    for (int e = 0; e < 4; e++) oacc[nf][e] *= corr[e >> 1];
                // ---- PV
#pragma unroll
                for (int ks = 0; ks < 4; ks++) {
                    uint32_t pf[4];
                    pf[0] = pack_f16(sacc[2 * ks][0], sacc[2 * ks][1]);
                    pf[1] = pack_f16(sacc[2 * ks][2], sacc[2 * ks][3]);
                    pf[2] = pack_f16(sacc[2 * ks + 1][0], sacc[2 * ks + 1][1]);
                    pf[3] = pack_f16(sacc[2 * ks + 1][2], sacc[2 * ks + 1][3]);
                    uint32_t vf[4][4];
#pragma unroll
                    for (int g = 0; g < 4; g++) {
                        const uint32_t rb = kvb + 9216 +
                            ((ks * 16 + (lane & 15)) * 72 + g * 16 + (lane >> 4) * 8) * 2;
                        ldm_x4_t(vf[g], rb);
                    }
#pragma unroll
                    for (int nf = 0; nf < 8; nf++) {
                        const int g = nf >> 1, o = (nf & 1) * 2;
                        uint32_t bf[2] = {vf[g][o], vf[g][o + 1]};
                        mma16816h(oacc[nf], pf, bf);
                    }
                }
            }
        }

        // write ao as fp16 (input of out-proj GEMM)
        const int bb = bh >> 3, h = bh & 7;
#pragma unroll
        for (int r = 0; r < 2; r++) {
            const float inv = 1.f / lrow[r];
            const int qi = qi0 + r * 8;
            const size_t rowoff = ((size_t)bb * SEQ + qi) * DMODEL + h * HDIM;
#pragma unroll
            for (int nf = 0; nf < 8; nf++) {
                const int hd = nf * 8 + (lane & 3) * 2;
                *reinterpret_cast<uint32_t*>(g_aof + rowoff + hd) =
                    pack_f16(oacc[nf][r * 2] * inv, oacc[nf][r * 2 + 1] * inv);
            }
        }
    }
}

// ---------------------------------------------------------------- launch
extern "C" void kernel_launch(void* const* d_in, const int* in_sizes, int n_in,
                              void* d_out, int out_size) {
    const float* x     = (const float*)d_in[0];
    const float* w_qkv = (const float*)d_in[1];
    const float* b_qkv = (const float*)d_in[2];
    const float* w_out = (const float*)d_in[3];
    const float* b_out = (const float*)d_in[4];
    float* out = (float*)d_out;

    __half *xf, *wqf, *wof, *aof;
    cudaGetSymbolAddress((void**)&xf, g_xf);
    cudaGetSymbolAddress((void**)&wqf, g_wqf);
    cudaGetSymbolAddress((void**)&wof, g_wof);
    cudaGetSymbolAddress((void**)&aof, g_aof);

    const int SMEM_GEMM = 3 * GSTG;      // 56832
    const int SMEM_ATT  = 36864 + 3 * 18432;  // 92160
    cudaFuncSetAttribute(gemm_f16<0>, cudaFuncAttributeMaxDynamicSharedMemorySize, SMEM_GEMM);
    cudaFuncSetAttribute(gemm_f16<1>, cudaFuncAttributeMaxDynamicSharedMemorySize, SMEM_GEMM);
    cudaFuncSetAttribute(attn_mma,    cudaFuncAttributeMaxDynamicSharedMemorySize, SMEM_ATT);

    // fused pre-convert (x, w_qkv, w_out -> fp16)
    convert_all<<<(N4_TOT + 255) / 256, 256>>>(
        (const float4*)x, (const float4*)w_qkv, (const float4*)w_out);

    // 1) QKV projection -> q/k/v fp16 (Q pre-scaled by 0.125*log2e)
    gemm_f16<0><<<dim3(QKV_N / 128, MROWS / 128), 256, SMEM_GEMM>>>(
        xf, wqf, b_qkv, nullptr, QKV_N);
    // 2) causal attention (fp16, log2-domain softmax, balanced wave) -> g_aof
    attn_mma<<<dim3(4, BATCH * NHEAD), 512, SMEM_ATT>>>();
    // 3) output projection -> fp32 out
    gemm_f16<1><<<dim3(DMODEL / 128, MROWS / 128), 256, SMEM_GEMM>>>(
        aof, wof, b_out, out, DMODEL);
}